// round 3
// baseline (speedup 1.0000x reference)
#include <cuda_runtime.h>
#include <cstdint>

// ----------------------------------------------------------------------------
// RecursiveBlock: channel attention + CSWin attention, b=16, DIM=128, 64x64 fp32
// Channel attn expands to 256 channels (8 heads x 32); qkv has 768 rows.
// R2: double-buffered SGEMM (1 sync/K-step), fused cs qk+v GEMM (M=384).
// ----------------------------------------------------------------------------

typedef unsigned long long u64;

#define DEVFN __device__ __forceinline__

DEVFN u64 ffma2(u64 a, u64 b, u64 c) {
    u64 r; asm("fma.rn.f32x2 %0, %1, %2, %3;" : "=l"(r) : "l"(a), "l"(b), "l"(c)); return r;
}
DEVFN u64 fmul2(u64 a, u64 b) {
    u64 r; asm("mul.rn.f32x2 %0, %1, %2;" : "=l"(r) : "l"(a), "l"(b)); return r;
}
DEVFN u64 pack2(float lo, float hi) {
    u64 r; asm("mov.b64 %0, {%1, %2};" : "=l"(r) : "f"(lo), "f"(hi)); return r;
}
DEVFN float2 unpack2(u64 v) {
    float lo, hi; asm("mov.b64 {%0, %1}, %2;" : "=f"(lo), "=f"(hi) : "l"(v));
    return make_float2(lo, hi);
}

// Fast exp on the FMA pipe (avoids MUFU, rt=8/SMSP on B300). rel err ~6e-6.
DEVFN float fast_exp(float x) {
    float t = x * 1.4426950408889634f;
    t = fmaxf(t, -126.0f);
    float fi = floorf(t);
    float f = t - fi;
    float p = 1.5403530e-4f;
    p = fmaf(p, f, 1.3333558e-3f);
    p = fmaf(p, f, 9.6181291e-3f);
    p = fmaf(p, f, 5.5504109e-2f);
    p = fmaf(p, f, 2.4022651e-1f);
    p = fmaf(p, f, 6.9314718e-1f);
    p = fmaf(p, f, 1.0f);
    return p * __int_as_float(((int)fi + 127) << 23);
}

// ----------------------------------------------------------------------------
// Scratch buffers
// ----------------------------------------------------------------------------
#define NB 16
#define NSP 4096   // 64*64

__device__ float g_qkv [NB * 768 * NSP];   // channel-attn qkv (q:0-255, k:256-511, v:512-767)
__device__ float g_norm[NB * 8 * 64];      // inverse L2 norms per (b,h): q rows 0..31, k rows 32..63
__device__ float g_gram[NB * 8 * 32 * 32]; // raw Q.K^T
__device__ float g_catt[NB * 8 * 32 * 32]; // softmaxed channel attention
__device__ float g_M   [NB * 128 * 256];   // proj_w @ blockdiag(attn) fold
__device__ float g_x2  [NB * 128 * NSP];   // x + channel_attention(x)
__device__ float g_cs  [NB * 384 * NSP];   // cswin qk (0-255) | v (256-383)
__device__ float g_lepe[NB * 64 * NSP];    // v_v lepe
__device__ float g_att [NB * 128 * NSP];   // cswin attention output (pre-proj)
__device__ float g_wcat[384 * 128];        // [cs_qk_w ; cs_v_w]

// ----------------------------------------------------------------------------
// Weight concat: wcat = [cs_qk_w (256x128) ; cs_v_w (128x128)]
// ----------------------------------------------------------------------------
__global__ void __launch_bounds__(256) concat_w_kernel(const float* __restrict__ qk_w,
                                                       const float* __restrict__ v_w,
                                                       float* __restrict__ wcat)
{
    int i = blockIdx.x * 256 + threadIdx.x;   // 0..49151
    wcat[i] = (i < 256 * 128) ? qk_w[i] : v_w[i - 256 * 128];
}

// ----------------------------------------------------------------------------
// Generic batched SGEMM: C[b] = (Res?[b] +) A[b](M,K) @ B[b](K,N), N = 4096.
// 128x128 tile, BK=8 double-buffered (single sync per K-step), 256 threads,
// 8x8 micro-tile as f32x2 pairs.
// ----------------------------------------------------------------------------
template <int RESID>
__global__ void __launch_bounds__(256, 2) sgemm_kernel(
    const float* __restrict__ A, const float* __restrict__ B,
    const float* __restrict__ R, float* __restrict__ C,
    int M, int K, long long sA, long long sB, long long sR, long long sC)
{
    const int N = 4096;
    int bz = blockIdx.z;
    A += bz * sA; B += bz * sB; C += bz * sC;
    if (RESID) R += bz * sR;

    int mBase = blockIdx.y * 128;
    int nBase = blockIdx.x * 128;

    __shared__ float As[2][8][128];
    __shared__ float Bs[2][8][128];

    int tid  = threadIdx.x;
    int aRow = tid >> 1;          // 0..127
    int aCol = (tid & 1) << 2;    // 0 or 4
    int bRow = tid >> 5;          // 0..7
    int bCol = (tid & 31) << 2;   // 0..124
    int tx = tid & 15, ty = tid >> 4;

    u64 acc[8][4];
#pragma unroll
    for (int i = 0; i < 8; i++)
#pragma unroll
        for (int j = 0; j < 4; j++) acc[i][j] = 0ull;

    const bool aValid = (mBase + aRow) < M;
    const float* Aptr = A + (long long)(mBase + aRow) * K + aCol;
    const float* Bptr = B + (long long)bRow * N + nBase + bCol;

    const int ntiles = K >> 3;

    float4 av = make_float4(0.f, 0.f, 0.f, 0.f);
    if (aValid) av = *(const float4*)(Aptr);
    float4 bv = *(const float4*)(Bptr);

    for (int i = 0; i < ntiles; i++) {
        int p = i & 1;
        As[p][aCol + 0][aRow] = av.x;
        As[p][aCol + 1][aRow] = av.y;
        As[p][aCol + 2][aRow] = av.z;
        As[p][aCol + 3][aRow] = av.w;
        *(float4*)&Bs[p][bRow][bCol] = bv;
        __syncthreads();

        if (i + 1 < ntiles) {   // prefetch next tile; latency hidden by compute below
            av = make_float4(0.f, 0.f, 0.f, 0.f);
            if (aValid) av = *(const float4*)(Aptr + (i + 1) * 8);
            bv = *(const float4*)(Bptr + (long long)(i + 1) * 8 * N);
        }

#pragma unroll
        for (int kk = 0; kk < 8; kk++) {
            float4 aLo = *(float4*)&As[p][kk][ty * 4];
            float4 aHi = *(float4*)&As[p][kk][64 + ty * 4];
            float4 bLo = *(float4*)&Bs[p][kk][tx * 4];
            float4 bHi = *(float4*)&Bs[p][kk][64 + tx * 4];
            u64 b2[4];
            b2[0] = pack2(bLo.x, bLo.y); b2[1] = pack2(bLo.z, bLo.w);
            b2[2] = pack2(bHi.x, bHi.y); b2[3] = pack2(bHi.z, bHi.w);
            float a[8] = {aLo.x, aLo.y, aLo.z, aLo.w, aHi.x, aHi.y, aHi.z, aHi.w};
#pragma unroll
            for (int ii = 0; ii < 8; ii++) {
                u64 ad = pack2(a[ii], a[ii]);
#pragma unroll
                for (int j = 0; j < 4; j++) acc[ii][j] = ffma2(ad, b2[j], acc[ii][j]);
            }
        }
        // no second sync: next store targets the other buffer, last read
        // before the sync above — safe with one barrier per K-step.
    }

#pragma unroll
    for (int i = 0; i < 8; i++) {
        int m = mBase + ((i < 4) ? (ty * 4 + i) : (64 + ty * 4 + (i - 4)));
        if (m < M) {
            long long rowoff = (long long)m * N + nBase;
#pragma unroll
            for (int half = 0; half < 2; half++) {
                int col = (half == 0) ? (tx * 4) : (64 + tx * 4);
                float2 p0 = unpack2(acc[i][half * 2 + 0]);
                float2 p1 = unpack2(acc[i][half * 2 + 1]);
                float4 v = make_float4(p0.x, p0.y, p1.x, p1.y);
                if (RESID) {
                    float4 rv = *(const float4*)&R[rowoff + col];
                    v.x += rv.x; v.y += rv.y; v.z += rv.z; v.w += rv.w;
                }
                *(float4*)&C[rowoff + col] = v;
            }
        }
    }
}

// ----------------------------------------------------------------------------
// Channel attention: inverse L2 norms of q/k rows (8192 rows of 4096)
// ----------------------------------------------------------------------------
__global__ void __launch_bounds__(256) norm_kernel(const float* __restrict__ qkv,
                                                   float* __restrict__ norminv)
{
    int warp = threadIdx.x >> 5, lane = threadIdx.x & 31;
    int row = blockIdx.x * 8 + warp;          // 0..8191
    int bh = row >> 6;
    int r  = row & 63;
    int b = bh >> 3, h = bh & 7;
    int ch = (r < 32) ? (h * 32 + r) : (256 + h * 32 + (r - 32));
    const float* p = qkv + ((long long)b * 768 + ch) * NSP;
    float ss = 0.f;
    for (int i = lane; i < NSP; i += 32) { float v = p[i]; ss = fmaf(v, v, ss); }
#pragma unroll
    for (int off = 16; off > 0; off >>= 1) ss += __shfl_xor_sync(0xffffffffu, ss, off);
    if (lane == 0) norminv[row] = 1.0f / fmaxf(sqrtf(ss), 1e-12f);
}

// ----------------------------------------------------------------------------
// Gram: G[b][h] = Q(32,4096) @ K(32,4096)^T.  Block (16x16), 2x2 micro-tile.
// ----------------------------------------------------------------------------
__global__ void __launch_bounds__(256) gram_kernel(const float* __restrict__ qkv,
                                                   float* __restrict__ G)
{
    int bh = blockIdx.x;                       // 0..127
    int b = bh >> 3, h = bh & 7;
    const float* Q  = qkv + ((long long)b * 768 + h * 32) * NSP;
    const float* Kp = qkv + ((long long)b * 768 + 256 + h * 32) * NSP;

    __shared__ float Qs[32 * 68];
    __shared__ float Ks[32 * 68];

    int tx = threadIdx.x & 15, ty = threadIdx.x >> 4;
    float a00 = 0.f, a01 = 0.f, a10 = 0.f, a11 = 0.f;

    for (int c0 = 0; c0 < NSP; c0 += 64) {
        __syncthreads();
        for (int l = threadIdx.x; l < 2048; l += 256) {
            int r = l >> 6, cc = l & 63;
            Qs[r * 68 + cc] = Q[(long long)r * NSP + c0 + cc];
            Ks[r * 68 + cc] = Kp[(long long)r * NSP + c0 + cc];
        }
        __syncthreads();
#pragma unroll
        for (int tt = 0; tt < 64; tt += 4) {
            float4 q0 = *(float4*)&Qs[ty * 68 + tt];
            float4 q1 = *(float4*)&Qs[(ty + 16) * 68 + tt];
            float4 k0 = *(float4*)&Ks[tx * 68 + tt];
            float4 k1 = *(float4*)&Ks[(tx + 16) * 68 + tt];
            a00 = fmaf(q0.x, k0.x, fmaf(q0.y, k0.y, fmaf(q0.z, k0.z, fmaf(q0.w, k0.w, a00))));
            a01 = fmaf(q0.x, k1.x, fmaf(q0.y, k1.y, fmaf(q0.z, k1.z, fmaf(q0.w, k1.w, a01))));
            a10 = fmaf(q1.x, k0.x, fmaf(q1.y, k0.y, fmaf(q1.z, k0.z, fmaf(q1.w, k0.w, a10))));
            a11 = fmaf(q1.x, k1.x, fmaf(q1.y, k1.y, fmaf(q1.z, k1.z, fmaf(q1.w, k1.w, a11))));
        }
    }
    float* g = G + (long long)bh * 1024;
    g[ty * 32 + tx]              = a00;
    g[ty * 32 + tx + 16]         = a01;
    g[(ty + 16) * 32 + tx]       = a10;
    g[(ty + 16) * 32 + tx + 16]  = a11;
}

// ----------------------------------------------------------------------------
// Channel-attn softmax (32-wide rows)
// ----------------------------------------------------------------------------
__global__ void __launch_bounds__(1024) ca_softmax_kernel(
    const float* __restrict__ G, const float* __restrict__ norminv,
    const float* __restrict__ temp, float* __restrict__ attn)
{
    int bh = blockIdx.x;
    int h = bh & 7;
    int j = threadIdx.x & 31, i = threadIdx.x >> 5;
    float qi = norminv[bh * 64 + i];
    float kj = norminv[bh * 64 + 32 + j];
    float l = G[(long long)bh * 1024 + i * 32 + j] * qi * kj * temp[h];
    float m = l;
#pragma unroll
    for (int off = 16; off > 0; off >>= 1) m = fmaxf(m, __shfl_xor_sync(0xffffffffu, m, off));
    float p = fast_exp(l - m);
    float s = p;
#pragma unroll
    for (int off = 16; off > 0; off >>= 1) s += __shfl_xor_sync(0xffffffffu, s, off);
    attn[(long long)bh * 1024 + i * 32 + j] = p / s;
}

// ----------------------------------------------------------------------------
// Fold: M_b[o][h*32+j] = sum_i proj_w[o][h*32+i] * attn[b][h][i][j]
// ----------------------------------------------------------------------------
__global__ void __launch_bounds__(256) fold_kernel(const float* __restrict__ attn,
                                                   const float* __restrict__ proj_w,
                                                   float* __restrict__ Mfold)
{
    int b = blockIdx.x;
    __shared__ float As[8192];
    for (int l = threadIdx.x; l < 8192; l += 256) As[l] = attn[(long long)b * 8192 + l];
    __syncthreads();
    for (int idx = threadIdx.x; idx < 32768; idx += 256) {
        int o = idx >> 8, c = idx & 255;
        int h = c >> 5, j = c & 31;
        const float* pw = proj_w + o * 256 + h * 32;
        const float* at = As + h * 1024 + j;
        float s = 0.f;
#pragma unroll
        for (int i = 0; i < 32; i++) s = fmaf(pw[i], at[i * 32], s);
        Mfold[(long long)b * 32768 + idx] = s;
    }
}

// ----------------------------------------------------------------------------
// CSWin window attention over combined cs buffer (384 rows/batch).
// DIR=0: horizontal (64x4), q rows h*8, k 128+h*8, v 256+h*8, lepe=v.
// DIR=1: vertical (4x64),  q 64+h*8, k 192+h*8, v 320+h*8, lepe buffer.
// ----------------------------------------------------------------------------
template <int DIR>
__global__ void __launch_bounds__(256) cswin_kernel(
    const float* __restrict__ cs, const float* __restrict__ lepe,
    float* __restrict__ outp)
{
    int win = blockIdx.x, h = blockIdx.y, b = blockIdx.z;
    int t = threadIdx.x;

    long long cb = (long long)b * 384 * NSP;
    long long ob = (long long)b * 128 * NSP;
    int n;
    const float *qp, *kp, *vp, *lp;
    float* op;
    if (DIR == 0) {
        n  = ((t >> 2) << 6) + (win << 2) + (t & 3);
        qp = cs + cb + (long long)(h * 8) * NSP;
        kp = cs + cb + (long long)(128 + h * 8) * NSP;
        vp = cs + cb + (long long)(256 + h * 8) * NSP;
        lp = vp;  // v_h_lepe = v_h
        op = outp + ob + (long long)(h * 8) * NSP;
    } else {
        n  = (((win << 2) + (t >> 6)) << 6) + (t & 63);
        qp = cs + cb + (long long)(64 + h * 8) * NSP;
        kp = cs + cb + (long long)(192 + h * 8) * NSP;
        vp = cs + cb + (long long)(320 + h * 8) * NSP;
        lp = lepe + (long long)b * 64 * NSP + (long long)(h * 8) * NSP;
        op = outp + ob + (long long)(64 + h * 8) * NSP;
    }

    __shared__ float4 Ks[256][2];
    __shared__ float4 Vs[256][2];

    float q[8], lep[8], kr[8], vr[8];
#pragma unroll
    for (int d = 0; d < 8; d++) {
        q[d]   = qp[d * NSP + n] * 0.25f;    // scale = (128/8)^-0.5
        kr[d]  = kp[d * NSP + n];
        vr[d]  = vp[d * NSP + n];
        lep[d] = lp[d * NSP + n];
    }
    Ks[t][0] = make_float4(kr[0], kr[1], kr[2], kr[3]);
    Ks[t][1] = make_float4(kr[4], kr[5], kr[6], kr[7]);
    Vs[t][0] = make_float4(vr[0], vr[1], vr[2], vr[3]);
    Vs[t][1] = make_float4(vr[4], vr[5], vr[6], vr[7]);

    u64 q2[4];
    q2[0] = pack2(q[0], q[1]); q2[1] = pack2(q[2], q[3]);
    q2[2] = pack2(q[4], q[5]); q2[3] = pack2(q[6], q[7]);
    __syncthreads();

    u64 acc[4] = {0ull, 0ull, 0ull, 0ull};
    float ssum = 0.f;
#pragma unroll 4
    for (int j = 0; j < 256; j++) {
        ulonglong2 ka = *(const ulonglong2*)&Ks[j][0];
        ulonglong2 kb = *(const ulonglong2*)&Ks[j][1];
        u64 s2 = fmul2(q2[0], ka.x);
        s2 = ffma2(q2[1], ka.y, s2);
        s2 = ffma2(q2[2], kb.x, s2);
        s2 = ffma2(q2[3], kb.y, s2);
        float2 sf = unpack2(s2);
        float sc = sf.x + sf.y;
        float p = fast_exp(fminf(sc, 60.f));
        ssum += p;
        u64 p2 = pack2(p, p);
        ulonglong2 va  = *(const ulonglong2*)&Vs[j][0];
        ulonglong2 vb2 = *(const ulonglong2*)&Vs[j][1];
        acc[0] = ffma2(p2, va.x,  acc[0]);
        acc[1] = ffma2(p2, va.y,  acc[1]);
        acc[2] = ffma2(p2, vb2.x, acc[2]);
        acc[3] = ffma2(p2, vb2.y, acc[3]);
    }

    float inv = 1.0f / ssum;
#pragma unroll
    for (int dp = 0; dp < 4; dp++) {
        float2 a = unpack2(acc[dp]);
        op[(dp * 2 + 0) * NSP + n] = fmaf(a.x, inv, lep[dp * 2 + 0]);
        op[(dp * 2 + 1) * NSP + n] = fmaf(a.y, inv, lep[dp * 2 + 1]);
    }
}

// ----------------------------------------------------------------------------
// Launch chain
// ----------------------------------------------------------------------------
extern "C" void kernel_launch(void* const* d_in, const int* in_sizes, int n_in,
                              void* d_out, int out_size)
{
    const float* x         = (const float*)d_in[0];
    const float* ca_temp   = (const float*)d_in[1];
    const float* ca_qkv_w  = (const float*)d_in[2];
    const float* ca_proj_w = (const float*)d_in[3];
    const float* cs_qk_w   = (const float*)d_in[4];
    const float* cs_v_w    = (const float*)d_in[5];
    const float* cs_vv_w   = (const float*)d_in[6];
    // d_in[7] = cs_vh_w (unused by reference)
    const float* cs_proj_w = (const float*)d_in[8];
    float* out = (float*)d_out;

    float *qkv, *nrm, *gram, *catt, *Mf, *x2, *cs, *lep, *att, *wcat;
    cudaGetSymbolAddress((void**)&qkv,  g_qkv);
    cudaGetSymbolAddress((void**)&nrm,  g_norm);
    cudaGetSymbolAddress((void**)&gram, g_gram);
    cudaGetSymbolAddress((void**)&catt, g_catt);
    cudaGetSymbolAddress((void**)&Mf,   g_M);
    cudaGetSymbolAddress((void**)&x2,   g_x2);
    cudaGetSymbolAddress((void**)&cs,   g_cs);
    cudaGetSymbolAddress((void**)&lep,  g_lepe);
    cudaGetSymbolAddress((void**)&att,  g_att);
    cudaGetSymbolAddress((void**)&wcat, g_wcat);

    const long long S128 = 128LL * NSP, S384 = 384LL * NSP, S768 = 768LL * NSP, S64 = 64LL * NSP;

    // 0. weight concat for fused cswin qk|v GEMM
    concat_w_kernel<<<192, 256>>>(cs_qk_w, cs_v_w, wcat);
    // 1. qkv = ca_qkv_w @ x            (M=768, K=128)
    sgemm_kernel<0><<<dim3(32, 6, NB), 256>>>(ca_qkv_w, x, nullptr, qkv,
                                              768, 128, 0, S128, 0, S768);
    // 2. q/k row inverse norms
    norm_kernel<<<1024, 256>>>(qkv, nrm);
    // 3. Gram matrices
    gram_kernel<<<128, 256>>>(qkv, gram);
    // 4. channel-attn softmax
    ca_softmax_kernel<<<128, 1024>>>(gram, nrm, ca_temp, catt);
    // 5. fold proj_w through attention
    fold_kernel<<<NB, 256>>>(catt, ca_proj_w, Mf);
    // 6. x2 = x + M_b @ V              (M=128, K=256; V = qkv[512:768])
    sgemm_kernel<1><<<dim3(32, 1, NB), 256>>>(Mf, qkv + 512 * NSP, x, x2,
                                              128, 256, 32768, S768, S128, S128);
    // 7. cs = [cs_qk_w; cs_v_w] @ x2   (M=384, K=128) -> qk rows 0-255, v rows 256-383
    sgemm_kernel<0><<<dim3(32, 3, NB), 256>>>(wcat, x2, nullptr, cs,
                                              384, 128, 0, S128, 0, S384);
    // 8. lepe_v = cs_vv_w @ v_v        (M=64, K=64; v_v = cs rows 320-383)
    sgemm_kernel<0><<<dim3(32, 1, NB), 256>>>(cs_vv_w, cs + 320 * NSP, nullptr, lep,
                                              64, 64, 0, S384, 0, S64);
    // 9/10. CSWin attention, both directions
    cswin_kernel<0><<<dim3(16, 8, NB), 256>>>(cs, lep, att);
    cswin_kernel<1><<<dim3(16, 8, NB), 256>>>(cs, lep, att);
    // 11. out = x2 + cs_proj_w @ att   (M=128, K=128)
    sgemm_kernel<1><<<dim3(32, 1, NB), 256>>>(cs_proj_w, att, x2, out,
                                              128, 128, 0, S128, S128, S128);

    (void)in_sizes; (void)n_in; (void)out_size;
}

// round 4
// speedup vs baseline: 1.0924x; 1.0924x over previous
#include <cuda_runtime.h>
#include <cstdint>

// ----------------------------------------------------------------------------
// RecursiveBlock: channel attention + CSWin attention, b=16, DIM=128, 64x64 fp32
// R3: chunked gram (grid 1024) with fused row sum-of-squares (norm kernel gone);
//     SGEMM reads B pairs as ulonglong2 from smem (no pack MOVs).
// ----------------------------------------------------------------------------

typedef unsigned long long u64;

#define DEVFN __device__ __forceinline__

DEVFN u64 ffma2(u64 a, u64 b, u64 c) {
    u64 r; asm("fma.rn.f32x2 %0, %1, %2, %3;" : "=l"(r) : "l"(a), "l"(b), "l"(c)); return r;
}
DEVFN u64 fmul2(u64 a, u64 b) {
    u64 r; asm("mul.rn.f32x2 %0, %1, %2;" : "=l"(r) : "l"(a), "l"(b)); return r;
}
DEVFN u64 pack2(float lo, float hi) {
    u64 r; asm("mov.b64 %0, {%1, %2};" : "=l"(r) : "f"(lo), "f"(hi)); return r;
}
DEVFN float2 unpack2(u64 v) {
    float lo, hi; asm("mov.b64 {%0, %1}, %2;" : "=f"(lo), "=f"(hi) : "l"(v));
    return make_float2(lo, hi);
}

// Fast exp on the FMA pipe (avoids MUFU). rel err ~6e-6.
DEVFN float fast_exp(float x) {
    float t = x * 1.4426950408889634f;
    t = fmaxf(t, -126.0f);
    float fi = floorf(t);
    float f = t - fi;
    float p = 1.5403530e-4f;
    p = fmaf(p, f, 1.3333558e-3f);
    p = fmaf(p, f, 9.6181291e-3f);
    p = fmaf(p, f, 5.5504109e-2f);
    p = fmaf(p, f, 2.4022651e-1f);
    p = fmaf(p, f, 6.9314718e-1f);
    p = fmaf(p, f, 1.0f);
    return p * __int_as_float(((int)fi + 127) << 23);
}

// ----------------------------------------------------------------------------
// Scratch buffers
// ----------------------------------------------------------------------------
#define NB 16
#define NSP 4096   // 64*64
#define NCH 8      // gram spatial chunks

__device__ float g_qkv [NB * 768 * NSP];     // q:0-255, k:256-511, v:512-767
__device__ float g_gpart[128 * NCH * 1088];  // per-chunk: G(1024) + sumsq(64: q 0-31, k 32-63)
__device__ float g_catt[NB * 8 * 32 * 32];   // softmaxed channel attention
__device__ float g_M   [NB * 128 * 256];     // proj_w @ blockdiag(attn) fold
__device__ float g_x2  [NB * 128 * NSP];     // x + channel_attention(x)
__device__ float g_cs  [NB * 384 * NSP];     // cswin qk (0-255) | v (256-383)
__device__ float g_lepe[NB * 64 * NSP];      // v_v lepe
__device__ float g_att [NB * 128 * NSP];     // cswin attention output (pre-proj)
__device__ float g_wcat[384 * 128];          // [cs_qk_w ; cs_v_w]

// ----------------------------------------------------------------------------
// Weight concat: wcat = [cs_qk_w (256x128) ; cs_v_w (128x128)]
// ----------------------------------------------------------------------------
__global__ void __launch_bounds__(256) concat_w_kernel(const float* __restrict__ qk_w,
                                                       const float* __restrict__ v_w,
                                                       float* __restrict__ wcat)
{
    int i = blockIdx.x * 256 + threadIdx.x;
    wcat[i] = (i < 256 * 128) ? qk_w[i] : v_w[i - 256 * 128];
}

// ----------------------------------------------------------------------------
// Generic batched SGEMM: C[b] = (Res?[b] +) A[b](M,K) @ B[b](K,N), N = 4096.
// 128x128 tile, BK=8 double-buffered, 256 threads, 8x8 micro-tile (f32x2).
// ----------------------------------------------------------------------------
template <int RESID>
__global__ void __launch_bounds__(256, 2) sgemm_kernel(
    const float* __restrict__ A, const float* __restrict__ B,
    const float* __restrict__ R, float* __restrict__ C,
    int M, int K, long long sA, long long sB, long long sR, long long sC)
{
    const int N = 4096;
    int bz = blockIdx.z;
    A += bz * sA; B += bz * sB; C += bz * sC;
    if (RESID) R += bz * sR;

    int mBase = blockIdx.y * 128;
    int nBase = blockIdx.x * 128;

    __shared__ __align__(16) float As[2][8][128];
    __shared__ __align__(16) float Bs[2][8][128];

    int tid  = threadIdx.x;
    int aRow = tid >> 1;
    int aCol = (tid & 1) << 2;
    int bRow = tid >> 5;
    int bCol = (tid & 31) << 2;
    int tx = tid & 15, ty = tid >> 4;

    u64 acc[8][4];
#pragma unroll
    for (int i = 0; i < 8; i++)
#pragma unroll
        for (int j = 0; j < 4; j++) acc[i][j] = 0ull;

    const bool aValid = (mBase + aRow) < M;
    const float* Aptr = A + (long long)(mBase + aRow) * K + aCol;
    const float* Bptr = B + (long long)bRow * N + nBase + bCol;

    const int ntiles = K >> 3;

    float4 av = make_float4(0.f, 0.f, 0.f, 0.f);
    if (aValid) av = *(const float4*)(Aptr);
    float4 bv = *(const float4*)(Bptr);

    for (int i = 0; i < ntiles; i++) {
        int p = i & 1;
        As[p][aCol + 0][aRow] = av.x;
        As[p][aCol + 1][aRow] = av.y;
        As[p][aCol + 2][aRow] = av.z;
        As[p][aCol + 3][aRow] = av.w;
        *(float4*)&Bs[p][bRow][bCol] = bv;
        __syncthreads();

        if (i + 1 < ntiles) {
            av = make_float4(0.f, 0.f, 0.f, 0.f);
            if (aValid) av = *(const float4*)(Aptr + (i + 1) * 8);
            bv = *(const float4*)(Bptr + (long long)(i + 1) * 8 * N);
        }

#pragma unroll
        for (int kk = 0; kk < 8; kk++) {
            float4 aLo = *(float4*)&As[p][kk][ty * 4];
            float4 aHi = *(float4*)&As[p][kk][64 + ty * 4];
            // B pairs read directly as 64-bit lanes — no pack MOVs
            ulonglong2 bl = *(const ulonglong2*)&Bs[p][kk][tx * 4];
            ulonglong2 bh = *(const ulonglong2*)&Bs[p][kk][64 + tx * 4];
            u64 b2[4] = {bl.x, bl.y, bh.x, bh.y};
            float a[8] = {aLo.x, aLo.y, aLo.z, aLo.w, aHi.x, aHi.y, aHi.z, aHi.w};
#pragma unroll
            for (int ii = 0; ii < 8; ii++) {
                u64 ad = pack2(a[ii], a[ii]);
#pragma unroll
                for (int j = 0; j < 4; j++) acc[ii][j] = ffma2(ad, b2[j], acc[ii][j]);
            }
        }
    }

#pragma unroll
    for (int i = 0; i < 8; i++) {
        int m = mBase + ((i < 4) ? (ty * 4 + i) : (64 + ty * 4 + (i - 4)));
        if (m < M) {
            long long rowoff = (long long)m * N + nBase;
#pragma unroll
            for (int half = 0; half < 2; half++) {
                int col = (half == 0) ? (tx * 4) : (64 + tx * 4);
                float2 p0 = unpack2(acc[i][half * 2 + 0]);
                float2 p1 = unpack2(acc[i][half * 2 + 1]);
                float4 v = make_float4(p0.x, p0.y, p1.x, p1.y);
                if (RESID) {
                    float4 rv = *(const float4*)&R[rowoff + col];
                    v.x += rv.x; v.y += rv.y; v.z += rv.z; v.w += rv.w;
                }
                *(float4*)&C[rowoff + col] = v;
            }
        }
    }
}

// ----------------------------------------------------------------------------
// Chunked Gram + fused sum-of-squares.
// grid (NCH, 128): block handles 512 spatial cols for one (b,h).
// Emits partial G (32x32) and partial sumsq for the 32 q rows + 32 k rows.
// ----------------------------------------------------------------------------
__global__ void __launch_bounds__(256) gram_partial_kernel(const float* __restrict__ qkv,
                                                           float* __restrict__ gpart)
{
    int chunk = blockIdx.x;                    // 0..NCH-1
    int bh = blockIdx.y;                       // 0..127
    int b = bh >> 3, h = bh & 7;
    const float* Q  = qkv + ((long long)b * 768 + h * 32) * NSP;
    const float* Kp = qkv + ((long long)b * 768 + 256 + h * 32) * NSP;

    __shared__ float Qs[32 * 68];
    __shared__ float Ks[32 * 68];

    int tx = threadIdx.x & 15, ty = threadIdx.x >> 4;
    int r4 = threadIdx.x >> 2;                 // 0..63 (row for sumsq)
    int quad = threadIdx.x & 3;
    float a00 = 0.f, a01 = 0.f, a10 = 0.f, a11 = 0.f;
    float ssq = 0.f;

    int c_beg = chunk * (NSP / NCH);
    for (int c0 = c_beg; c0 < c_beg + (NSP / NCH); c0 += 64) {
        __syncthreads();
        for (int l = threadIdx.x; l < 2048; l += 256) {
            int r = l >> 6, cc = l & 63;
            Qs[r * 68 + cc] = Q[(long long)r * NSP + c0 + cc];
            Ks[r * 68 + cc] = Kp[(long long)r * NSP + c0 + cc];
        }
        __syncthreads();
#pragma unroll
        for (int tt = 0; tt < 64; tt += 4) {
            float4 q0 = *(float4*)&Qs[ty * 68 + tt];
            float4 q1 = *(float4*)&Qs[(ty + 16) * 68 + tt];
            float4 k0 = *(float4*)&Ks[tx * 68 + tt];
            float4 k1 = *(float4*)&Ks[(tx + 16) * 68 + tt];
            a00 = fmaf(q0.x, k0.x, fmaf(q0.y, k0.y, fmaf(q0.z, k0.z, fmaf(q0.w, k0.w, a00))));
            a01 = fmaf(q0.x, k1.x, fmaf(q0.y, k1.y, fmaf(q0.z, k1.z, fmaf(q0.w, k1.w, a01))));
            a10 = fmaf(q1.x, k0.x, fmaf(q1.y, k0.y, fmaf(q1.z, k0.z, fmaf(q1.w, k0.w, a10))));
            a11 = fmaf(q1.x, k1.x, fmaf(q1.y, k1.y, fmaf(q1.z, k1.z, fmaf(q1.w, k1.w, a11))));
        }
        // fused sum-of-squares: thread quad sums 16 cols of its row
        const float* src = (r4 < 32) ? &Qs[r4 * 68] : &Ks[(r4 - 32) * 68];
#pragma unroll
        for (int e = 0; e < 16; e++) {
            float v = src[quad * 16 + e];
            ssq = fmaf(v, v, ssq);
        }
    }
    ssq += __shfl_xor_sync(0xffffffffu, ssq, 1);
    ssq += __shfl_xor_sync(0xffffffffu, ssq, 2);

    float* out = gpart + ((long long)bh * NCH + chunk) * 1088;
    out[ty * 32 + tx]               = a00;
    out[ty * 32 + tx + 16]          = a01;
    out[(ty + 16) * 32 + tx]        = a10;
    out[(ty + 16) * 32 + tx + 16]   = a11;
    if (quad == 0) out[1024 + r4] = ssq;
}

// ----------------------------------------------------------------------------
// Channel-attn softmax: reduce gram partials + norms, softmax 32-wide rows.
// ----------------------------------------------------------------------------
__global__ void __launch_bounds__(1024) ca_softmax_kernel(
    const float* __restrict__ gpart, const float* __restrict__ temp,
    float* __restrict__ attn)
{
    int bh = blockIdx.x;
    int h = bh & 7;
    int t = threadIdx.x;
    const float* base = gpart + (long long)bh * NCH * 1088;

    __shared__ float ninv[64];
    if (t < 64) {
        float ss = 0.f;
#pragma unroll
        for (int c = 0; c < NCH; c++) ss += base[c * 1088 + 1024 + t];
        ninv[t] = 1.0f / fmaxf(sqrtf(ss), 1e-12f);
    }

    int i = t >> 5, j = t & 31;
    float g = 0.f;
#pragma unroll
    for (int c = 0; c < NCH; c++) g += base[c * 1088 + i * 32 + j];
    __syncthreads();

    float l = g * ninv[i] * ninv[32 + j] * temp[h];
    float m = l;
#pragma unroll
    for (int off = 16; off > 0; off >>= 1) m = fmaxf(m, __shfl_xor_sync(0xffffffffu, m, off));
    float p = fast_exp(l - m);
    float s = p;
#pragma unroll
    for (int off = 16; off > 0; off >>= 1) s += __shfl_xor_sync(0xffffffffu, s, off);
    attn[(long long)bh * 1024 + i * 32 + j] = p / s;
}

// ----------------------------------------------------------------------------
// Fold: M_b[o][h*32+j] = sum_i proj_w[o][h*32+i] * attn[b][h][i][j]
// ----------------------------------------------------------------------------
__global__ void __launch_bounds__(256) fold_kernel(const float* __restrict__ attn,
                                                   const float* __restrict__ proj_w,
                                                   float* __restrict__ Mfold)
{
    int b = blockIdx.x;
    __shared__ float As[8192];
    for (int l = threadIdx.x; l < 8192; l += 256) As[l] = attn[(long long)b * 8192 + l];
    __syncthreads();
    for (int idx = threadIdx.x; idx < 32768; idx += 256) {
        int o = idx >> 8, c = idx & 255;
        int h = c >> 5, j = c & 31;
        const float* pw = proj_w + o * 256 + h * 32;
        const float* at = As + h * 1024 + j;
        float s = 0.f;
#pragma unroll
        for (int i = 0; i < 32; i++) s = fmaf(pw[i], at[i * 32], s);
        Mfold[(long long)b * 32768 + idx] = s;
    }
}

// ----------------------------------------------------------------------------
// CSWin window attention over combined cs buffer (384 rows/batch).
// ----------------------------------------------------------------------------
template <int DIR>
__global__ void __launch_bounds__(256) cswin_kernel(
    const float* __restrict__ cs, const float* __restrict__ lepe,
    float* __restrict__ outp)
{
    int win = blockIdx.x, h = blockIdx.y, b = blockIdx.z;
    int t = threadIdx.x;

    long long cb = (long long)b * 384 * NSP;
    long long ob = (long long)b * 128 * NSP;
    int n;
    const float *qp, *kp, *vp, *lp;
    float* op;
    if (DIR == 0) {
        n  = ((t >> 2) << 6) + (win << 2) + (t & 3);
        qp = cs + cb + (long long)(h * 8) * NSP;
        kp = cs + cb + (long long)(128 + h * 8) * NSP;
        vp = cs + cb + (long long)(256 + h * 8) * NSP;
        lp = vp;
        op = outp + ob + (long long)(h * 8) * NSP;
    } else {
        n  = (((win << 2) + (t >> 6)) << 6) + (t & 63);
        qp = cs + cb + (long long)(64 + h * 8) * NSP;
        kp = cs + cb + (long long)(192 + h * 8) * NSP;
        vp = cs + cb + (long long)(320 + h * 8) * NSP;
        lp = lepe + (long long)b * 64 * NSP + (long long)(h * 8) * NSP;
        op = outp + ob + (long long)(64 + h * 8) * NSP;
    }

    __shared__ float4 Ks[256][2];
    __shared__ float4 Vs[256][2];

    float q[8], lep[8], kr[8], vr[8];
#pragma unroll
    for (int d = 0; d < 8; d++) {
        q[d]   = qp[d * NSP + n] * 0.25f;
        kr[d]  = kp[d * NSP + n];
        vr[d]  = vp[d * NSP + n];
        lep[d] = lp[d * NSP + n];
    }
    Ks[t][0] = make_float4(kr[0], kr[1], kr[2], kr[3]);
    Ks[t][1] = make_float4(kr[4], kr[5], kr[6], kr[7]);
    Vs[t][0] = make_float4(vr[0], vr[1], vr[2], vr[3]);
    Vs[t][1] = make_float4(vr[4], vr[5], vr[6], vr[7]);

    u64 q2[4];
    q2[0] = pack2(q[0], q[1]); q2[1] = pack2(q[2], q[3]);
    q2[2] = pack2(q[4], q[5]); q2[3] = pack2(q[6], q[7]);
    __syncthreads();

    u64 acc[4] = {0ull, 0ull, 0ull, 0ull};
    float ssum = 0.f;
#pragma unroll 4
    for (int j = 0; j < 256; j++) {
        ulonglong2 ka = *(const ulonglong2*)&Ks[j][0];
        ulonglong2 kb = *(const ulonglong2*)&Ks[j][1];
        u64 s2 = fmul2(q2[0], ka.x);
        s2 = ffma2(q2[1], ka.y, s2);
        s2 = ffma2(q2[2], kb.x, s2);
        s2 = ffma2(q2[3], kb.y, s2);
        float2 sf = unpack2(s2);
        float sc = sf.x + sf.y;
        float p = fast_exp(fminf(sc, 60.f));
        ssum += p;
        u64 p2 = pack2(p, p);
        ulonglong2 va  = *(const ulonglong2*)&Vs[j][0];
        ulonglong2 vb2 = *(const ulonglong2*)&Vs[j][1];
        acc[0] = ffma2(p2, va.x,  acc[0]);
        acc[1] = ffma2(p2, va.y,  acc[1]);
        acc[2] = ffma2(p2, vb2.x, acc[2]);
        acc[3] = ffma2(p2, vb2.y, acc[3]);
    }

    float inv = 1.0f / ssum;
#pragma unroll
    for (int dp = 0; dp < 4; dp++) {
        float2 a = unpack2(acc[dp]);
        op[(dp * 2 + 0) * NSP + n] = fmaf(a.x, inv, lep[dp * 2 + 0]);
        op[(dp * 2 + 1) * NSP + n] = fmaf(a.y, inv, lep[dp * 2 + 1]);
    }
}

// ----------------------------------------------------------------------------
// Launch chain
// ----------------------------------------------------------------------------
extern "C" void kernel_launch(void* const* d_in, const int* in_sizes, int n_in,
                              void* d_out, int out_size)
{
    const float* x         = (const float*)d_in[0];
    const float* ca_temp   = (const float*)d_in[1];
    const float* ca_qkv_w  = (const float*)d_in[2];
    const float* ca_proj_w = (const float*)d_in[3];
    const float* cs_qk_w   = (const float*)d_in[4];
    const float* cs_v_w    = (const float*)d_in[5];
    const float* cs_vv_w   = (const float*)d_in[6];
    const float* cs_proj_w = (const float*)d_in[8];
    float* out = (float*)d_out;

    float *qkv, *gp, *catt, *Mf, *x2, *cs, *lep, *att, *wcat;
    cudaGetSymbolAddress((void**)&qkv,  g_qkv);
    cudaGetSymbolAddress((void**)&gp,   g_gpart);
    cudaGetSymbolAddress((void**)&catt, g_catt);
    cudaGetSymbolAddress((void**)&Mf,   g_M);
    cudaGetSymbolAddress((void**)&x2,   g_x2);
    cudaGetSymbolAddress((void**)&cs,   g_cs);
    cudaGetSymbolAddress((void**)&lep,  g_lepe);
    cudaGetSymbolAddress((void**)&att,  g_att);
    cudaGetSymbolAddress((void**)&wcat, g_wcat);

    const long long S128 = 128LL * NSP, S384 = 384LL * NSP, S768 = 768LL * NSP, S64 = 64LL * NSP;

    // 0. weight concat for fused cswin qk|v GEMM
    concat_w_kernel<<<192, 256>>>(cs_qk_w, cs_v_w, wcat);
    // 1. qkv = ca_qkv_w @ x            (M=768, K=128)
    sgemm_kernel<0><<<dim3(32, 6, NB), 256>>>(ca_qkv_w, x, nullptr, qkv,
                                              768, 128, 0, S128, 0, S768);
    // 2. chunked gram + sumsq
    gram_partial_kernel<<<dim3(NCH, 128), 256>>>(qkv, gp);
    // 3. channel-attn softmax (reduces partials + norms)
    ca_softmax_kernel<<<128, 1024>>>(gp, ca_temp, catt);
    // 4. fold proj_w through attention
    fold_kernel<<<NB, 256>>>(catt, ca_proj_w, Mf);
    // 5. x2 = x + M_b @ V              (M=128, K=256; V = qkv[512:768])
    sgemm_kernel<1><<<dim3(32, 1, NB), 256>>>(Mf, qkv + 512 * NSP, x, x2,
                                              128, 256, 32768, S768, S128, S128);
    // 6. cs = [cs_qk_w; cs_v_w] @ x2   (M=384, K=128)
    sgemm_kernel<0><<<dim3(32, 3, NB), 256>>>(wcat, x2, nullptr, cs,
                                              384, 128, 0, S128, 0, S384);
    // 7. lepe_v = cs_vv_w @ v_v        (M=64, K=64; v_v = cs rows 320-383)
    sgemm_kernel<0><<<dim3(32, 1, NB), 256>>>(cs_vv_w, cs + 320 * NSP, nullptr, lep,
                                              64, 64, 0, S384, 0, S64);
    // 8/9. CSWin attention, both directions
    cswin_kernel<0><<<dim3(16, 8, NB), 256>>>(cs, lep, att);
    cswin_kernel<1><<<dim3(16, 8, NB), 256>>>(cs, lep, att);
    // 10. out = x2 + cs_proj_w @ att   (M=128, K=128)
    sgemm_kernel<1><<<dim3(32, 1, NB), 256>>>(cs_proj_w, att, x2, out,
                                              128, 128, 0, S128, S128, S128);

    (void)in_sizes; (void)n_in; (void)out_size;
}

// round 6
// speedup vs baseline: 1.3085x; 1.1978x over previous
#include <cuda_runtime.h>
#include <cuda_bf16.h>
#include <cstdint>

// ----------------------------------------------------------------------------
// RecursiveBlock: channel attention + CSWin attention, b=16, DIM=128, 64x64 fp32
// R6: mma.sync bf16 hi/lo 3-pass GEMM (tcgen05 unavailable: harness targets
// plain sm_103, no arch-accelerated features).
// ----------------------------------------------------------------------------

typedef unsigned long long u64;

#define DEVFN __device__ __forceinline__

DEVFN u64 ffma2(u64 a, u64 b, u64 c) {
    u64 r; asm("fma.rn.f32x2 %0, %1, %2, %3;" : "=l"(r) : "l"(a), "l"(b), "l"(c)); return r;
}
DEVFN u64 fmul2(u64 a, u64 b) {
    u64 r; asm("mul.rn.f32x2 %0, %1, %2;" : "=l"(r) : "l"(a), "l"(b)); return r;
}
DEVFN u64 pack2(float lo, float hi) {
    u64 r; asm("mov.b64 %0, {%1, %2};" : "=l"(r) : "f"(lo), "f"(hi)); return r;
}
DEVFN float2 unpack2(u64 v) {
    float lo, hi; asm("mov.b64 {%0, %1}, %2;" : "=f"(lo), "=f"(hi) : "l"(v));
    return make_float2(lo, hi);
}

DEVFN float fast_exp(float x) {
    float t = x * 1.4426950408889634f;
    t = fmaxf(t, -126.0f);
    float fi = floorf(t);
    float f = t - fi;
    float p = 1.5403530e-4f;
    p = fmaf(p, f, 1.3333558e-3f);
    p = fmaf(p, f, 9.6181291e-3f);
    p = fmaf(p, f, 5.5504109e-2f);
    p = fmaf(p, f, 2.4022651e-1f);
    p = fmaf(p, f, 6.9314718e-1f);
    p = fmaf(p, f, 1.0f);
    return p * __int_as_float(((int)fi + 127) << 23);
}

DEVFN uint32_t smem_u32(const void* p) {
    uint32_t a;
    asm("{ .reg .u64 t; cvta.to.shared.u64 t, %1; cvt.u32.u64 %0, t; }" : "=r"(a) : "l"(p));
    return a;
}
DEVFN void ldsm_x4(uint32_t* r, uint32_t addr) {
    asm volatile("ldmatrix.sync.aligned.m8n8.x4.shared.b16 {%0,%1,%2,%3}, [%4];"
                 : "=r"(r[0]), "=r"(r[1]), "=r"(r[2]), "=r"(r[3]) : "r"(addr));
}
DEVFN void ldsm_x4_t(uint32_t* r, uint32_t addr) {
    asm volatile("ldmatrix.sync.aligned.m8n8.x4.trans.shared.b16 {%0,%1,%2,%3}, [%4];"
                 : "=r"(r[0]), "=r"(r[1]), "=r"(r[2]), "=r"(r[3]) : "r"(addr));
}
DEVFN void mma_bf16(float* c, const uint32_t* a, uint32_t b0, uint32_t b1) {
    asm volatile(
        "mma.sync.aligned.m16n8k16.row.col.f32.bf16.bf16.f32 "
        "{%0,%1,%2,%3}, {%4,%5,%6,%7}, {%8,%9}, {%0,%1,%2,%3};"
        : "+f"(c[0]), "+f"(c[1]), "+f"(c[2]), "+f"(c[3])
        : "r"(a[0]), "r"(a[1]), "r"(a[2]), "r"(a[3]), "r"(b0), "r"(b1));
}
DEVFN uint32_t bfpack(float a, float b) {
    __nv_bfloat162 t = __floats2bfloat162_rn(a, b);
    return *(uint32_t*)&t;
}

// ----------------------------------------------------------------------------
// Scratch buffers
// ----------------------------------------------------------------------------
#define NB 16
#define NSP 4096
#define NCH 8

__device__ float g_qkv [NB * 768 * NSP];
__device__ float g_gpart[128 * NCH * 1088];
__device__ float g_catt[NB * 8 * 32 * 32];
__device__ float g_M   [NB * 128 * 256];
__device__ float g_x2  [NB * 128 * NSP];
__device__ float g_cs  [NB * 384 * NSP];
__device__ float g_lepe[NB * 64 * NSP];
__device__ float g_att [NB * 128 * NSP];
__device__ float g_wcat[384 * 128];

__global__ void __launch_bounds__(256) concat_w_kernel(const float* __restrict__ qk_w,
                                                       const float* __restrict__ v_w,
                                                       float* __restrict__ wcat)
{
    int i = blockIdx.x * 256 + threadIdx.x;
    wcat[i] = (i < 256 * 128) ? qk_w[i] : v_w[i - 256 * 128];
}

// ----------------------------------------------------------------------------
// mma.sync GEMM: C[b](M,4096) = (R?) + A[b](M,K) @ B[b](K,4096)
// 128x128 tile, K chunks of 128. bf16 hi/lo split, 3 passes, fp32 accum.
// smem: A[m][k] and B[k][n] bf16, row stride 136 elems (272 B = 4-bank shift
// -> ldmatrix 8-row fetches conflict-free). A frags via ldmatrix.x4,
// B frags via ldmatrix.x4.trans (no smem transpose).
// M must be a multiple of 128 (true for all call sites).
// ----------------------------------------------------------------------------
#define RS_B 272                 // row stride bytes (136 bf16)
#define MAT_BYTES (128 * RS_B)   // 34816
#define MG_SMEM (4 * MAT_BYTES)  // 139264

template <int RESID>
__global__ void __launch_bounds__(256) mgemm_kernel(
    const float* __restrict__ A, const float* __restrict__ B,
    const float* __restrict__ R, float* __restrict__ C,
    int M, int K, long long sA, long long sB, long long sR, long long sC)
{
    extern __shared__ char smem[];
    char* pAh = smem;
    char* pAl = smem + MAT_BYTES;
    char* pBh = smem + 2 * MAT_BYTES;
    char* pBl = smem + 3 * MAT_BYTES;
    uint32_t aAh = smem_u32(pAh), aAl = smem_u32(pAl);
    uint32_t aBh = smem_u32(pBh), aBl = smem_u32(pBl);

    int tid = threadIdx.x, wid = tid >> 5, lane = tid & 31;
    int nBase = blockIdx.x * 128;
    int mBase = blockIdx.y * 128;
    int bz = blockIdx.z;
    A += bz * sA; B += bz * sB; C += bz * sC;
    if (RESID) R += bz * sR;

    int mw = (wid >> 1) * 32;    // warp row base within tile
    int nw = (wid & 1) * 64;     // warp col base within tile

    float acc[2][8][4];
#pragma unroll
    for (int t = 0; t < 2; t++)
#pragma unroll
        for (int n = 0; n < 8; n++)
#pragma unroll
            for (int e = 0; e < 4; e++) acc[t][n][e] = 0.f;

    int lrow = lane & 7;
    int lm8  = (lane >> 3) & 1;
    int lk8  = lane >> 4;

    for (int k0 = 0; k0 < K; k0 += 128) {
        // ---- fill A: [m][k] hi/lo ----
        for (int idx = tid; idx < 4096; idx += 256) {
            int m = idx >> 5, kq = (idx & 31) << 2;
            float4 v = *(const float4*)&A[(long long)(mBase + m) * K + k0 + kq];
            float hx = __bfloat162float(__float2bfloat16(v.x));
            float hy = __bfloat162float(__float2bfloat16(v.y));
            float hz = __bfloat162float(__float2bfloat16(v.z));
            float hw = __bfloat162float(__float2bfloat16(v.w));
            int off = m * RS_B + kq * 2;
            *(uint2*)(pAh + off) = make_uint2(bfpack(hx, hy), bfpack(hz, hw));
            *(uint2*)(pAl + off) = make_uint2(bfpack(v.x - hx, v.y - hy),
                                              bfpack(v.z - hz, v.w - hw));
        }
        // ---- fill B: [k][n] hi/lo ----
        for (int idx = tid; idx < 4096; idx += 256) {
            int k = idx >> 5, nq = (idx & 31) << 2;
            float4 v = *(const float4*)&B[(long long)(k0 + k) * 4096 + nBase + nq];
            float hx = __bfloat162float(__float2bfloat16(v.x));
            float hy = __bfloat162float(__float2bfloat16(v.y));
            float hz = __bfloat162float(__float2bfloat16(v.z));
            float hw = __bfloat162float(__float2bfloat16(v.w));
            int off = k * RS_B + nq * 2;
            *(uint2*)(pBh + off) = make_uint2(bfpack(hx, hy), bfpack(hz, hw));
            *(uint2*)(pBl + off) = make_uint2(bfpack(v.x - hx, v.y - hy),
                                              bfpack(v.z - hz, v.w - hw));
        }
        __syncthreads();

#pragma unroll
        for (int ks = 0; ks < 8; ks++) {
            // A fragments: 2 m-tiles, hi + lo
            uint32_t ah[2][4], al[2][4];
#pragma unroll
            for (int t = 0; t < 2; t++) {
                int m = mw + t * 16 + lrow + lm8 * 8;
                int k = ks * 16 + lk8 * 8;
                uint32_t off = (uint32_t)(m * RS_B + k * 2);
                ldsm_x4(ah[t], aAh + off);
                ldsm_x4(al[t], aAl + off);
            }
            // B fragments: 4 n-pairs (16 cols each), hi + lo
#pragma unroll
            for (int np = 0; np < 4; np++) {
                int k = ks * 16 + lm8 * 8 + lrow;
                int n = nw + np * 16 + lk8 * 8;
                uint32_t off = (uint32_t)(k * RS_B + n * 2);
                uint32_t bh[4], bl[4];
                ldsm_x4_t(bh, aBh + off);
                ldsm_x4_t(bl, aBl + off);
#pragma unroll
                for (int t = 0; t < 2; t++) {
                    mma_bf16(acc[t][np * 2],     ah[t], bh[0], bh[1]);
                    mma_bf16(acc[t][np * 2],     ah[t], bl[0], bl[1]);
                    mma_bf16(acc[t][np * 2],     al[t], bh[0], bh[1]);
                    mma_bf16(acc[t][np * 2 + 1], ah[t], bh[2], bh[3]);
                    mma_bf16(acc[t][np * 2 + 1], ah[t], bl[2], bl[3]);
                    mma_bf16(acc[t][np * 2 + 1], al[t], bh[2], bh[3]);
                }
            }
        }
        __syncthreads();
    }

    // ---- epilogue ----
    int gid = lane >> 2, tig = lane & 3;
#pragma unroll
    for (int t = 0; t < 2; t++) {
#pragma unroll
        for (int nt = 0; nt < 8; nt++) {
            int row = mBase + mw + t * 16 + gid;
            int col = nBase + nw + nt * 8 + tig * 2;
            long long o0 = (long long)row * 4096 + col;
            long long o1 = (long long)(row + 8) * 4096 + col;
            float2 v0 = make_float2(acc[t][nt][0], acc[t][nt][1]);
            float2 v1 = make_float2(acc[t][nt][2], acc[t][nt][3]);
            if (RESID) {
                float2 r0 = *(const float2*)&R[o0];
                float2 r1 = *(const float2*)&R[o1];
                v0.x += r0.x; v0.y += r0.y; v1.x += r1.x; v1.y += r1.y;
            }
            *(float2*)&C[o0] = v0;
            *(float2*)&C[o1] = v1;
        }
    }
}

// ----------------------------------------------------------------------------
// Scalar SGEMM (kept for lepe: M=64, K=64)
// ----------------------------------------------------------------------------
template <int RESID>
__global__ void __launch_bounds__(256, 2) sgemm_kernel(
    const float* __restrict__ A, const float* __restrict__ B,
    const float* __restrict__ R, float* __restrict__ C,
    int M, int K, long long sA, long long sB, long long sR, long long sC)
{
    const int N = 4096;
    int bz = blockIdx.z;
    A += bz * sA; B += bz * sB; C += bz * sC;
    if (RESID) R += bz * sR;

    int mBase = blockIdx.y * 128;
    int nBase = blockIdx.x * 128;

    __shared__ __align__(16) float As[2][8][128];
    __shared__ __align__(16) float Bs[2][8][128];

    int tid  = threadIdx.x;
    int aRow = tid >> 1;
    int aCol = (tid & 1) << 2;
    int bRow = tid >> 5;
    int bCol = (tid & 31) << 2;
    int tx = tid & 15, ty = tid >> 4;

    u64 acc[8][4];
#pragma unroll
    for (int i = 0; i < 8; i++)
#pragma unroll
        for (int j = 0; j < 4; j++) acc[i][j] = 0ull;

    const bool aValid = (mBase + aRow) < M;
    const float* Aptr = A + (long long)(mBase + aRow) * K + aCol;
    const float* Bptr = B + (long long)bRow * N + nBase + bCol;

    const int ntiles = K >> 3;

    float4 av = make_float4(0.f, 0.f, 0.f, 0.f);
    if (aValid) av = *(const float4*)(Aptr);
    float4 bv = *(const float4*)(Bptr);

    for (int i = 0; i < ntiles; i++) {
        int p = i & 1;
        As[p][aCol + 0][aRow] = av.x;
        As[p][aCol + 1][aRow] = av.y;
        As[p][aCol + 2][aRow] = av.z;
        As[p][aCol + 3][aRow] = av.w;
        *(float4*)&Bs[p][bRow][bCol] = bv;
        __syncthreads();

        if (i + 1 < ntiles) {
            av = make_float4(0.f, 0.f, 0.f, 0.f);
            if (aValid) av = *(const float4*)(Aptr + (i + 1) * 8);
            bv = *(const float4*)(Bptr + (long long)(i + 1) * 8 * N);
        }

#pragma unroll
        for (int kk = 0; kk < 8; kk++) {
            float4 aLo = *(float4*)&As[p][kk][ty * 4];
            float4 aHi = *(float4*)&As[p][kk][64 + ty * 4];
            ulonglong2 bl = *(const ulonglong2*)&Bs[p][kk][tx * 4];
            ulonglong2 bh = *(const ulonglong2*)&Bs[p][kk][64 + tx * 4];
            u64 b2[4] = {bl.x, bl.y, bh.x, bh.y};
            float a[8] = {aLo.x, aLo.y, aLo.z, aLo.w, aHi.x, aHi.y, aHi.z, aHi.w};
#pragma unroll
            for (int ii = 0; ii < 8; ii++) {
                u64 ad = pack2(a[ii], a[ii]);
#pragma unroll
                for (int j = 0; j < 4; j++) acc[ii][j] = ffma2(ad, b2[j], acc[ii][j]);
            }
        }
    }

#pragma unroll
    for (int i = 0; i < 8; i++) {
        int m = mBase + ((i < 4) ? (ty * 4 + i) : (64 + ty * 4 + (i - 4)));
        if (m < M) {
            long long rowoff = (long long)m * N + nBase;
#pragma unroll
            for (int half = 0; half < 2; half++) {
                int col = (half == 0) ? (tx * 4) : (64 + tx * 4);
                float2 p0 = unpack2(acc[i][half * 2 + 0]);
                float2 p1 = unpack2(acc[i][half * 2 + 1]);
                float4 v = make_float4(p0.x, p0.y, p1.x, p1.y);
                if (RESID) {
                    float4 rv = *(const float4*)&R[rowoff + col];
                    v.x += rv.x; v.y += rv.y; v.z += rv.z; v.w += rv.w;
                }
                *(float4*)&C[rowoff + col] = v;
            }
        }
    }
}

// ----------------------------------------------------------------------------
// Chunked Gram + fused sum-of-squares
// ----------------------------------------------------------------------------
__global__ void __launch_bounds__(256) gram_partial_kernel(const float* __restrict__ qkv,
                                                           float* __restrict__ gpart)
{
    int chunk = blockIdx.x;
    int bh = blockIdx.y;
    int b = bh >> 3, h = bh & 7;
    const float* Q  = qkv + ((long long)b * 768 + h * 32) * NSP;
    const float* Kp = qkv + ((long long)b * 768 + 256 + h * 32) * NSP;

    __shared__ float Qs[32 * 68];
    __shared__ float Ks[32 * 68];

    int tx = threadIdx.x & 15, ty = threadIdx.x >> 4;
    int r4 = threadIdx.x >> 2;
    int quad = threadIdx.x & 3;
    float a00 = 0.f, a01 = 0.f, a10 = 0.f, a11 = 0.f;
    float ssq = 0.f;

    int c_beg = chunk * (NSP / NCH);
    for (int c0 = c_beg; c0 < c_beg + (NSP / NCH); c0 += 64) {
        __syncthreads();
        for (int l = threadIdx.x; l < 2048; l += 256) {
            int r = l >> 6, cc = l & 63;
            Qs[r * 68 + cc] = Q[(long long)r * NSP + c0 + cc];
            Ks[r * 68 + cc] = Kp[(long long)r * NSP + c0 + cc];
        }
        __syncthreads();
#pragma unroll
        for (int tt = 0; tt < 64; tt += 4) {
            float4 q0 = *(float4*)&Qs[ty * 68 + tt];
            float4 q1 = *(float4*)&Qs[(ty + 16) * 68 + tt];
            float4 k0 = *(float4*)&Ks[tx * 68 + tt];
            float4 k1 = *(float4*)&Ks[(tx + 16) * 68 + tt];
            a00 = fmaf(q0.x, k0.x, fmaf(q0.y, k0.y, fmaf(q0.z, k0.z, fmaf(q0.w, k0.w, a00))));
            a01 = fmaf(q0.x, k1.x, fmaf(q0.y, k1.y, fmaf(q0.z, k1.z, fmaf(q0.w, k1.w, a01))));
            a10 = fmaf(q1.x, k0.x, fmaf(q1.y, k0.y, fmaf(q1.z, k0.z, fmaf(q1.w, k0.w, a10))));
            a11 = fmaf(q1.x, k1.x, fmaf(q1.y, k1.y, fmaf(q1.z, k1.z, fmaf(q1.w, k1.w, a11))));
        }
        const float* src = (r4 < 32) ? &Qs[r4 * 68] : &Ks[(r4 - 32) * 68];
#pragma unroll
        for (int e = 0; e < 16; e++) {
            float v = src[quad * 16 + e];
            ssq = fmaf(v, v, ssq);
        }
    }
    ssq += __shfl_xor_sync(0xffffffffu, ssq, 1);
    ssq += __shfl_xor_sync(0xffffffffu, ssq, 2);

    float* out = gpart + ((long long)bh * NCH + chunk) * 1088;
    out[ty * 32 + tx]               = a00;
    out[ty * 32 + tx + 16]          = a01;
    out[(ty + 16) * 32 + tx]        = a10;
    out[(ty + 16) * 32 + tx + 16]   = a11;
    if (quad == 0) out[1024 + r4] = ssq;
}

__global__ void __launch_bounds__(1024) ca_softmax_kernel(
    const float* __restrict__ gpart, const float* __restrict__ temp,
    float* __restrict__ attn)
{
    int bh = blockIdx.x;
    int h = bh & 7;
    int t = threadIdx.x;
    const float* base = gpart + (long long)bh * NCH * 1088;

    __shared__ float ninv[64];
    if (t < 64) {
        float ss = 0.f;
#pragma unroll
        for (int c = 0; c < NCH; c++) ss += base[c * 1088 + 1024 + t];
        ninv[t] = 1.0f / fmaxf(sqrtf(ss), 1e-12f);
    }

    int i = t >> 5, j = t & 31;
    float g = 0.f;
#pragma unroll
    for (int c = 0; c < NCH; c++) g += base[c * 1088 + i * 32 + j];
    __syncthreads();

    float l = g * ninv[i] * ninv[32 + j] * temp[h];
    float m = l;
#pragma unroll
    for (int off = 16; off > 0; off >>= 1) m = fmaxf(m, __shfl_xor_sync(0xffffffffu, m, off));
    float p = fast_exp(l - m);
    float s = p;
#pragma unroll
    for (int off = 16; off > 0; off >>= 1) s += __shfl_xor_sync(0xffffffffu, s, off);
    attn[(long long)bh * 1024 + i * 32 + j] = p / s;
}

__global__ void __launch_bounds__(256) fold_kernel(const float* __restrict__ attn,
                                                   const float* __restrict__ proj_w,
                                                   float* __restrict__ Mfold)
{
    int b = blockIdx.x;
    __shared__ float As[8192];
    for (int l = threadIdx.x; l < 8192; l += 256) As[l] = attn[(long long)b * 8192 + l];
    __syncthreads();
    for (int idx = threadIdx.x; idx < 32768; idx += 256) {
        int o = idx >> 8, c = idx & 255;
        int h = c >> 5, j = c & 31;
        const float* pw = proj_w + o * 256 + h * 32;
        const float* at = As + h * 1024 + j;
        float s = 0.f;
#pragma unroll
        for (int i = 0; i < 32; i++) s = fmaf(pw[i], at[i * 32], s);
        Mfold[(long long)b * 32768 + idx] = s;
    }
}

template <int DIR>
__global__ void __launch_bounds__(256) cswin_kernel(
    const float* __restrict__ cs, const float* __restrict__ lepe,
    float* __restrict__ outp)
{
    int win = blockIdx.x, h = blockIdx.y, b = blockIdx.z;
    int t = threadIdx.x;

    long long cb = (long long)b * 384 * NSP;
    long long ob = (long long)b * 128 * NSP;
    int n;
    const float *qp, *kp, *vp, *lp;
    float* op;
    if (DIR == 0) {
        n  = ((t >> 2) << 6) + (win << 2) + (t & 3);
        qp = cs + cb + (long long)(h * 8) * NSP;
        kp = cs + cb + (long long)(128 + h * 8) * NSP;
        vp = cs + cb + (long long)(256 + h * 8) * NSP;
        lp = vp;
        op = outp + ob + (long long)(h * 8) * NSP;
    } else {
        n  = (((win << 2) + (t >> 6)) << 6) + (t & 63);
        qp = cs + cb + (long long)(64 + h * 8) * NSP;
        kp = cs + cb + (long long)(192 + h * 8) * NSP;
        vp = cs + cb + (long long)(320 + h * 8) * NSP;
        lp = lepe + (long long)b * 64 * NSP + (long long)(h * 8) * NSP;
        op = outp + ob + (long long)(64 + h * 8) * NSP;
    }

    __shared__ float4 Ks[256][2];
    __shared__ float4 Vs[256][2];

    float q[8], lep[8], kr[8], vr[8];
#pragma unroll
    for (int d = 0; d < 8; d++) {
        q[d]   = qp[d * NSP + n] * 0.25f;
        kr[d]  = kp[d * NSP + n];
        vr[d]  = vp[d * NSP + n];
        lep[d] = lp[d * NSP + n];
    }
    Ks[t][0] = make_float4(kr[0], kr[1], kr[2], kr[3]);
    Ks[t][1] = make_float4(kr[4], kr[5], kr[6], kr[7]);
    Vs[t][0] = make_float4(vr[0], vr[1], vr[2], vr[3]);
    Vs[t][1] = make_float4(vr[4], vr[5], vr[6], vr[7]);

    u64 q2[4];
    q2[0] = pack2(q[0], q[1]); q2[1] = pack2(q[2], q[3]);
    q2[2] = pack2(q[4], q[5]); q2[3] = pack2(q[6], q[7]);
    __syncthreads();

    u64 acc[4] = {0ull, 0ull, 0ull, 0ull};
    float ssum = 0.f;
#pragma unroll 4
    for (int j = 0; j < 256; j++) {
        ulonglong2 ka = *(const ulonglong2*)&Ks[j][0];
        ulonglong2 kb = *(const ulonglong2*)&Ks[j][1];
        u64 s2 = fmul2(q2[0], ka.x);
        s2 = ffma2(q2[1], ka.y, s2);
        s2 = ffma2(q2[2], kb.x, s2);
        s2 = ffma2(q2[3], kb.y, s2);
        float2 sf = unpack2(s2);
        float sc = sf.x + sf.y;
        float p = fast_exp(fminf(sc, 60.f));
        ssum += p;
        u64 p2 = pack2(p, p);
        ulonglong2 va  = *(const ulonglong2*)&Vs[j][0];
        ulonglong2 vb2 = *(const ulonglong2*)&Vs[j][1];
        acc[0] = ffma2(p2, va.x,  acc[0]);
        acc[1] = ffma2(p2, va.y,  acc[1]);
        acc[2] = ffma2(p2, vb2.x, acc[2]);
        acc[3] = ffma2(p2, vb2.y, acc[3]);
    }

    float inv = 1.0f / ssum;
#pragma unroll
    for (int dp = 0; dp < 4; dp++) {
        float2 a = unpack2(acc[dp]);
        op[(dp * 2 + 0) * NSP + n] = fmaf(a.x, inv, lep[dp * 2 + 0]);
        op[(dp * 2 + 1) * NSP + n] = fmaf(a.y, inv, lep[dp * 2 + 1]);
    }
}

// ----------------------------------------------------------------------------
// Launch chain
// ----------------------------------------------------------------------------
extern "C" void kernel_launch(void* const* d_in, const int* in_sizes, int n_in,
                              void* d_out, int out_size)
{
    const float* x         = (const float*)d_in[0];
    const float* ca_temp   = (const float*)d_in[1];
    const float* ca_qkv_w  = (const float*)d_in[2];
    const float* ca_proj_w = (const float*)d_in[3];
    const float* cs_qk_w   = (const float*)d_in[4];
    const float* cs_v_w    = (const float*)d_in[5];
    const float* cs_vv_w   = (const float*)d_in[6];
    const float* cs_proj_w = (const float*)d_in[8];
    float* out = (float*)d_out;

    float *qkv, *gp, *catt, *Mf, *x2, *cs, *lep, *att, *wcat;
    cudaGetSymbolAddress((void**)&qkv,  g_qkv);
    cudaGetSymbolAddress((void**)&gp,   g_gpart);
    cudaGetSymbolAddress((void**)&catt, g_catt);
    cudaGetSymbolAddress((void**)&Mf,   g_M);
    cudaGetSymbolAddress((void**)&x2,   g_x2);
    cudaGetSymbolAddress((void**)&cs,   g_cs);
    cudaGetSymbolAddress((void**)&lep,  g_lepe);
    cudaGetSymbolAddress((void**)&att,  g_att);
    cudaGetSymbolAddress((void**)&wcat, g_wcat);

    cudaFuncSetAttribute(mgemm_kernel<0>, cudaFuncAttributeMaxDynamicSharedMemorySize, MG_SMEM);
    cudaFuncSetAttribute(mgemm_kernel<1>, cudaFuncAttributeMaxDynamicSharedMemorySize, MG_SMEM);

    const long long S128 = 128LL * NSP, S384 = 384LL * NSP, S768 = 768LL * NSP, S64 = 64LL * NSP;

    // 0. weight concat for fused cswin qk|v GEMM
    concat_w_kernel<<<192, 256>>>(cs_qk_w, cs_v_w, wcat);
    // 1. qkv = ca_qkv_w @ x            (M=768, K=128)  [mma]
    mgemm_kernel<0><<<dim3(32, 6, NB), 256, MG_SMEM>>>(ca_qkv_w, x, nullptr, qkv,
                                                       768, 128, 0, S128, 0, S768);
    // 2. chunked gram + sumsq
    gram_partial_kernel<<<dim3(NCH, 128), 256>>>(qkv, gp);
    // 3. channel-attn softmax
    ca_softmax_kernel<<<128, 1024>>>(gp, ca_temp, catt);
    // 4. fold proj_w through attention
    fold_kernel<<<NB, 256>>>(catt, ca_proj_w, Mf);
    // 5. x2 = x + M_b @ V              (M=128, K=256)  [mma]
    mgemm_kernel<1><<<dim3(32, 1, NB), 256, MG_SMEM>>>(Mf, qkv + 512 * NSP, x, x2,
                                                       128, 256, 32768, S768, S128, S128);
    // 6. cs = [cs_qk_w; cs_v_w] @ x2   (M=384, K=128)  [mma]
    mgemm_kernel<0><<<dim3(32, 3, NB), 256, MG_SMEM>>>(wcat, x2, nullptr, cs,
                                                       384, 128, 0, S128, 0, S384);
    // 7. lepe_v = cs_vv_w @ v_v        (M=64, K=64)    [scalar]
    sgemm_kernel<0><<<dim3(32, 1, NB), 256>>>(cs_vv_w, cs + 320 * NSP, nullptr, lep,
                                              64, 64, 0, S384, 0, S64);
    // 8/9. CSWin attention
    cswin_kernel<0><<<dim3(16, 8, NB), 256>>>(cs, lep, att);
    cswin_kernel<1><<<dim3(16, 8, NB), 256>>>(cs, lep, att);
    // 10. out = x2 + cs_proj_w @ att   (M=128, K=128)  [mma]
    mgemm_kernel<1><<<dim3(32, 1, NB), 256, MG_SMEM>>>(cs_proj_w, att, x2, out,
                                                       128, 128, 0, S128, S128, S128);

    (void)in_sizes; (void)n_in; (void)out_size;
}

// round 7
// speedup vs baseline: 1.3118x; 1.0025x over previous
#include <cuda_runtime.h>
#include <cuda_bf16.h>
#include <cstdint>

// ----------------------------------------------------------------------------
// RecursiveBlock: channel attention + CSWin attention, b=16, DIM=128, 64x64 fp32
// R7: q-tiled cswin (64 thr x 4 queries -> 4x less smem traffic);
//     mma.sync bf16 hi/lo 3-pass GEMM (R6).
// ----------------------------------------------------------------------------

typedef unsigned long long u64;

#define DEVFN __device__ __forceinline__

DEVFN u64 ffma2(u64 a, u64 b, u64 c) {
    u64 r; asm("fma.rn.f32x2 %0, %1, %2, %3;" : "=l"(r) : "l"(a), "l"(b), "l"(c)); return r;
}
DEVFN u64 fmul2(u64 a, u64 b) {
    u64 r; asm("mul.rn.f32x2 %0, %1, %2;" : "=l"(r) : "l"(a), "l"(b)); return r;
}
DEVFN u64 pack2(float lo, float hi) {
    u64 r; asm("mov.b64 %0, {%1, %2};" : "=l"(r) : "f"(lo), "f"(hi)); return r;
}
DEVFN float2 unpack2(u64 v) {
    float lo, hi; asm("mov.b64 {%0, %1}, %2;" : "=f"(lo), "=f"(hi) : "l"(v));
    return make_float2(lo, hi);
}

DEVFN float fast_exp(float x) {
    float t = x * 1.4426950408889634f;
    t = fmaxf(t, -126.0f);
    float fi = floorf(t);
    float f = t - fi;
    float p = 1.5403530e-4f;
    p = fmaf(p, f, 1.3333558e-3f);
    p = fmaf(p, f, 9.6181291e-3f);
    p = fmaf(p, f, 5.5504109e-2f);
    p = fmaf(p, f, 2.4022651e-1f);
    p = fmaf(p, f, 6.9314718e-1f);
    p = fmaf(p, f, 1.0f);
    return p * __int_as_float(((int)fi + 127) << 23);
}

DEVFN uint32_t smem_u32(const void* p) {
    uint32_t a;
    asm("{ .reg .u64 t; cvta.to.shared.u64 t, %1; cvt.u32.u64 %0, t; }" : "=r"(a) : "l"(p));
    return a;
}
DEVFN void ldsm_x4(uint32_t* r, uint32_t addr) {
    asm volatile("ldmatrix.sync.aligned.m8n8.x4.shared.b16 {%0,%1,%2,%3}, [%4];"
                 : "=r"(r[0]), "=r"(r[1]), "=r"(r[2]), "=r"(r[3]) : "r"(addr));
}
DEVFN void ldsm_x4_t(uint32_t* r, uint32_t addr) {
    asm volatile("ldmatrix.sync.aligned.m8n8.x4.trans.shared.b16 {%0,%1,%2,%3}, [%4];"
                 : "=r"(r[0]), "=r"(r[1]), "=r"(r[2]), "=r"(r[3]) : "r"(addr));
}
DEVFN void mma_bf16(float* c, const uint32_t* a, uint32_t b0, uint32_t b1) {
    asm volatile(
        "mma.sync.aligned.m16n8k16.row.col.f32.bf16.bf16.f32 "
        "{%0,%1,%2,%3}, {%4,%5,%6,%7}, {%8,%9}, {%0,%1,%2,%3};"
        : "+f"(c[0]), "+f"(c[1]), "+f"(c[2]), "+f"(c[3])
        : "r"(a[0]), "r"(a[1]), "r"(a[2]), "r"(a[3]), "r"(b0), "r"(b1));
}
DEVFN uint32_t bfpack(float a, float b) {
    __nv_bfloat162 t = __floats2bfloat162_rn(a, b);
    return *(uint32_t*)&t;
}

// ----------------------------------------------------------------------------
// Scratch buffers
// ----------------------------------------------------------------------------
#define NB 16
#define NSP 4096
#define NCH 8

__device__ float g_qkv [NB * 768 * NSP];
__device__ float g_gpart[128 * NCH * 1088];
__device__ float g_catt[NB * 8 * 32 * 32];
__device__ float g_M   [NB * 128 * 256];
__device__ float g_x2  [NB * 128 * NSP];
__device__ float g_cs  [NB * 384 * NSP];
__device__ float g_lepe[NB * 64 * NSP];
__device__ float g_att [NB * 128 * NSP];
__device__ float g_wcat[384 * 128];

__global__ void __launch_bounds__(256) concat_w_kernel(const float* __restrict__ qk_w,
                                                       const float* __restrict__ v_w,
                                                       float* __restrict__ wcat)
{
    int i = blockIdx.x * 256 + threadIdx.x;
    wcat[i] = (i < 256 * 128) ? qk_w[i] : v_w[i - 256 * 128];
}

// ----------------------------------------------------------------------------
// mma.sync GEMM (unchanged from R6)
// ----------------------------------------------------------------------------
#define RS_B 272
#define MAT_BYTES (128 * RS_B)
#define MG_SMEM (4 * MAT_BYTES)

template <int RESID>
__global__ void __launch_bounds__(256) mgemm_kernel(
    const float* __restrict__ A, const float* __restrict__ B,
    const float* __restrict__ R, float* __restrict__ C,
    int M, int K, long long sA, long long sB, long long sR, long long sC)
{
    extern __shared__ char smem[];
    char* pAh = smem;
    char* pAl = smem + MAT_BYTES;
    char* pBh = smem + 2 * MAT_BYTES;
    char* pBl = smem + 3 * MAT_BYTES;
    uint32_t aAh = smem_u32(pAh), aAl = smem_u32(pAl);
    uint32_t aBh = smem_u32(pBh), aBl = smem_u32(pBl);

    int tid = threadIdx.x, wid = tid >> 5, lane = tid & 31;
    int nBase = blockIdx.x * 128;
    int mBase = blockIdx.y * 128;
    int bz = blockIdx.z;
    A += bz * sA; B += bz * sB; C += bz * sC;
    if (RESID) R += bz * sR;

    int mw = (wid >> 1) * 32;
    int nw = (wid & 1) * 64;

    float acc[2][8][4];
#pragma unroll
    for (int t = 0; t < 2; t++)
#pragma unroll
        for (int n = 0; n < 8; n++)
#pragma unroll
            for (int e = 0; e < 4; e++) acc[t][n][e] = 0.f;

    int lrow = lane & 7;
    int lm8  = (lane >> 3) & 1;
    int lk8  = lane >> 4;

    for (int k0 = 0; k0 < K; k0 += 128) {
        for (int idx = tid; idx < 4096; idx += 256) {
            int m = idx >> 5, kq = (idx & 31) << 2;
            float4 v = *(const float4*)&A[(long long)(mBase + m) * K + k0 + kq];
            float hx = __bfloat162float(__float2bfloat16(v.x));
            float hy = __bfloat162float(__float2bfloat16(v.y));
            float hz = __bfloat162float(__float2bfloat16(v.z));
            float hw = __bfloat162float(__float2bfloat16(v.w));
            int off = m * RS_B + kq * 2;
            *(uint2*)(pAh + off) = make_uint2(bfpack(hx, hy), bfpack(hz, hw));
            *(uint2*)(pAl + off) = make_uint2(bfpack(v.x - hx, v.y - hy),
                                              bfpack(v.z - hz, v.w - hw));
        }
        for (int idx = tid; idx < 4096; idx += 256) {
            int k = idx >> 5, nq = (idx & 31) << 2;
            float4 v = *(const float4*)&B[(long long)(k0 + k) * 4096 + nBase + nq];
            float hx = __bfloat162float(__float2bfloat16(v.x));
            float hy = __bfloat162float(__float2bfloat16(v.y));
            float hz = __bfloat162float(__float2bfloat16(v.z));
            float hw = __bfloat162float(__float2bfloat16(v.w));
            int off = k * RS_B + nq * 2;
            *(uint2*)(pBh + off) = make_uint2(bfpack(hx, hy), bfpack(hz, hw));
            *(uint2*)(pBl + off) = make_uint2(bfpack(v.x - hx, v.y - hy),
                                              bfpack(v.z - hz, v.w - hw));
        }
        __syncthreads();

#pragma unroll
        for (int ks = 0; ks < 8; ks++) {
            uint32_t ah[2][4], al[2][4];
#pragma unroll
            for (int t = 0; t < 2; t++) {
                int m = mw + t * 16 + lrow + lm8 * 8;
                int k = ks * 16 + lk8 * 8;
                uint32_t off = (uint32_t)(m * RS_B + k * 2);
                ldsm_x4(ah[t], aAh + off);
                ldsm_x4(al[t], aAl + off);
            }
#pragma unroll
            for (int np = 0; np < 4; np++) {
                int k = ks * 16 + lm8 * 8 + lrow;
                int n = nw + np * 16 + lk8 * 8;
                uint32_t off = (uint32_t)(k * RS_B + n * 2);
                uint32_t bh[4], bl[4];
                ldsm_x4_t(bh, aBh + off);
                ldsm_x4_t(bl, aBl + off);
#pragma unroll
                for (int t = 0; t < 2; t++) {
                    mma_bf16(acc[t][np * 2],     ah[t], bh[0], bh[1]);
                    mma_bf16(acc[t][np * 2],     ah[t], bl[0], bl[1]);
                    mma_bf16(acc[t][np * 2],     al[t], bh[0], bh[1]);
                    mma_bf16(acc[t][np * 2 + 1], ah[t], bh[2], bh[3]);
                    mma_bf16(acc[t][np * 2 + 1], ah[t], bl[2], bl[3]);
                    mma_bf16(acc[t][np * 2 + 1], al[t], bh[2], bh[3]);
                }
            }
        }
        __syncthreads();
    }

    int gid = lane >> 2, tig = lane & 3;
#pragma unroll
    for (int t = 0; t < 2; t++) {
#pragma unroll
        for (int nt = 0; nt < 8; nt++) {
            int row = mBase + mw + t * 16 + gid;
            int col = nBase + nw + nt * 8 + tig * 2;
            long long o0 = (long long)row * 4096 + col;
            long long o1 = (long long)(row + 8) * 4096 + col;
            float2 v0 = make_float2(acc[t][nt][0], acc[t][nt][1]);
            float2 v1 = make_float2(acc[t][nt][2], acc[t][nt][3]);
            if (RESID) {
                float2 r0 = *(const float2*)&R[o0];
                float2 r1 = *(const float2*)&R[o1];
                v0.x += r0.x; v0.y += r0.y; v1.x += r1.x; v1.y += r1.y;
            }
            *(float2*)&C[o0] = v0;
            *(float2*)&C[o1] = v1;
        }
    }
}

// ----------------------------------------------------------------------------
// Scalar SGEMM (lepe)
// ----------------------------------------------------------------------------
template <int RESID>
__global__ void __launch_bounds__(256, 2) sgemm_kernel(
    const float* __restrict__ A, const float* __restrict__ B,
    const float* __restrict__ R, float* __restrict__ C,
    int M, int K, long long sA, long long sB, long long sR, long long sC)
{
    const int N = 4096;
    int bz = blockIdx.z;
    A += bz * sA; B += bz * sB; C += bz * sC;
    if (RESID) R += bz * sR;

    int mBase = blockIdx.y * 128;
    int nBase = blockIdx.x * 128;

    __shared__ __align__(16) float As[2][8][128];
    __shared__ __align__(16) float Bs[2][8][128];

    int tid  = threadIdx.x;
    int aRow = tid >> 1;
    int aCol = (tid & 1) << 2;
    int bRow = tid >> 5;
    int bCol = (tid & 31) << 2;
    int tx = tid & 15, ty = tid >> 4;

    u64 acc[8][4];
#pragma unroll
    for (int i = 0; i < 8; i++)
#pragma unroll
        for (int j = 0; j < 4; j++) acc[i][j] = 0ull;

    const bool aValid = (mBase + aRow) < M;
    const float* Aptr = A + (long long)(mBase + aRow) * K + aCol;
    const float* Bptr = B + (long long)bRow * N + nBase + bCol;

    const int ntiles = K >> 3;

    float4 av = make_float4(0.f, 0.f, 0.f, 0.f);
    if (aValid) av = *(const float4*)(Aptr);
    float4 bv = *(const float4*)(Bptr);

    for (int i = 0; i < ntiles; i++) {
        int p = i & 1;
        As[p][aCol + 0][aRow] = av.x;
        As[p][aCol + 1][aRow] = av.y;
        As[p][aCol + 2][aRow] = av.z;
        As[p][aCol + 3][aRow] = av.w;
        *(float4*)&Bs[p][bRow][bCol] = bv;
        __syncthreads();

        if (i + 1 < ntiles) {
            av = make_float4(0.f, 0.f, 0.f, 0.f);
            if (aValid) av = *(const float4*)(Aptr + (i + 1) * 8);
            bv = *(const float4*)(Bptr + (long long)(i + 1) * 8 * N);
        }

#pragma unroll
        for (int kk = 0; kk < 8; kk++) {
            float4 aLo = *(float4*)&As[p][kk][ty * 4];
            float4 aHi = *(float4*)&As[p][kk][64 + ty * 4];
            ulonglong2 bl = *(const ulonglong2*)&Bs[p][kk][tx * 4];
            ulonglong2 bh = *(const ulonglong2*)&Bs[p][kk][64 + tx * 4];
            u64 b2[4] = {bl.x, bl.y, bh.x, bh.y};
            float a[8] = {aLo.x, aLo.y, aLo.z, aLo.w, aHi.x, aHi.y, aHi.z, aHi.w};
#pragma unroll
            for (int ii = 0; ii < 8; ii++) {
                u64 ad = pack2(a[ii], a[ii]);
#pragma unroll
                for (int j = 0; j < 4; j++) acc[ii][j] = ffma2(ad, b2[j], acc[ii][j]);
            }
        }
    }

#pragma unroll
    for (int i = 0; i < 8; i++) {
        int m = mBase + ((i < 4) ? (ty * 4 + i) : (64 + ty * 4 + (i - 4)));
        if (m < M) {
            long long rowoff = (long long)m * N + nBase;
#pragma unroll
            for (int half = 0; half < 2; half++) {
                int col = (half == 0) ? (tx * 4) : (64 + tx * 4);
                float2 p0 = unpack2(acc[i][half * 2 + 0]);
                float2 p1 = unpack2(acc[i][half * 2 + 1]);
                float4 v = make_float4(p0.x, p0.y, p1.x, p1.y);
                if (RESID) {
                    float4 rv = *(const float4*)&R[rowoff + col];
                    v.x += rv.x; v.y += rv.y; v.z += rv.z; v.w += rv.w;
                }
                *(float4*)&C[rowoff + col] = v;
            }
        }
    }
}

// ----------------------------------------------------------------------------
// Chunked Gram + fused sum-of-squares
// ----------------------------------------------------------------------------
__global__ void __launch_bounds__(256) gram_partial_kernel(const float* __restrict__ qkv,
                                                           float* __restrict__ gpart)
{
    int chunk = blockIdx.x;
    int bh = blockIdx.y;
    int b = bh >> 3, h = bh & 7;
    const float* Q  = qkv + ((long long)b * 768 + h * 32) * NSP;
    const float* Kp = qkv + ((long long)b * 768 + 256 + h * 32) * NSP;

    __shared__ float Qs[32 * 68];
    __shared__ float Ks[32 * 68];

    int tx = threadIdx.x & 15, ty = threadIdx.x >> 4;
    int r4 = threadIdx.x >> 2;
    int quad = threadIdx.x & 3;
    float a00 = 0.f, a01 = 0.f, a10 = 0.f, a11 = 0.f;
    float ssq = 0.f;

    int c_beg = chunk * (NSP / NCH);
    for (int c0 = c_beg; c0 < c_beg + (NSP / NCH); c0 += 64) {
        __syncthreads();
        for (int l = threadIdx.x; l < 2048; l += 256) {
            int r = l >> 6, cc = l & 63;
            Qs[r * 68 + cc] = Q[(long long)r * NSP + c0 + cc];
            Ks[r * 68 + cc] = Kp[(long long)r * NSP + c0 + cc];
        }
        __syncthreads();
#pragma unroll
        for (int tt = 0; tt < 64; tt += 4) {
            float4 q0 = *(float4*)&Qs[ty * 68 + tt];
            float4 q1 = *(float4*)&Qs[(ty + 16) * 68 + tt];
            float4 k0 = *(float4*)&Ks[tx * 68 + tt];
            float4 k1 = *(float4*)&Ks[(tx + 16) * 68 + tt];
            a00 = fmaf(q0.x, k0.x, fmaf(q0.y, k0.y, fmaf(q0.z, k0.z, fmaf(q0.w, k0.w, a00))));
            a01 = fmaf(q0.x, k1.x, fmaf(q0.y, k1.y, fmaf(q0.z, k1.z, fmaf(q0.w, k1.w, a01))));
            a10 = fmaf(q1.x, k0.x, fmaf(q1.y, k0.y, fmaf(q1.z, k0.z, fmaf(q1.w, k0.w, a10))));
            a11 = fmaf(q1.x, k1.x, fmaf(q1.y, k1.y, fmaf(q1.z, k1.z, fmaf(q1.w, k1.w, a11))));
        }
        const float* src = (r4 < 32) ? &Qs[r4 * 68] : &Ks[(r4 - 32) * 68];
#pragma unroll
        for (int e = 0; e < 16; e++) {
            float v = src[quad * 16 + e];
            ssq = fmaf(v, v, ssq);
        }
    }
    ssq += __shfl_xor_sync(0xffffffffu, ssq, 1);
    ssq += __shfl_xor_sync(0xffffffffu, ssq, 2);

    float* out = gpart + ((long long)bh * NCH + chunk) * 1088;
    out[ty * 32 + tx]               = a00;
    out[ty * 32 + tx + 16]          = a01;
    out[(ty + 16) * 32 + tx]        = a10;
    out[(ty + 16) * 32 + tx + 16]   = a11;
    if (quad == 0) out[1024 + r4] = ssq;
}

__global__ void __launch_bounds__(1024) ca_softmax_kernel(
    const float* __restrict__ gpart, const float* __restrict__ temp,
    float* __restrict__ attn)
{
    int bh = blockIdx.x;
    int h = bh & 7;
    int t = threadIdx.x;
    const float* base = gpart + (long long)bh * NCH * 1088;

    __shared__ float ninv[64];
    if (t < 64) {
        float ss = 0.f;
#pragma unroll
        for (int c = 0; c < NCH; c++) ss += base[c * 1088 + 1024 + t];
        ninv[t] = 1.0f / fmaxf(sqrtf(ss), 1e-12f);
    }

    int i = t >> 5, j = t & 31;
    float g = 0.f;
#pragma unroll
    for (int c = 0; c < NCH; c++) g += base[c * 1088 + i * 32 + j];
    __syncthreads();

    float l = g * ninv[i] * ninv[32 + j] * temp[h];
    float m = l;
#pragma unroll
    for (int off = 16; off > 0; off >>= 1) m = fmaxf(m, __shfl_xor_sync(0xffffffffu, m, off));
    float p = fast_exp(l - m);
    float s = p;
#pragma unroll
    for (int off = 16; off > 0; off >>= 1) s += __shfl_xor_sync(0xffffffffu, s, off);
    attn[(long long)bh * 1024 + i * 32 + j] = p / s;
}

__global__ void __launch_bounds__(256) fold_kernel(const float* __restrict__ attn,
                                                   const float* __restrict__ proj_w,
                                                   float* __restrict__ Mfold)
{
    int b = blockIdx.x;
    __shared__ float As[8192];
    for (int l = threadIdx.x; l < 8192; l += 256) As[l] = attn[(long long)b * 8192 + l];
    __syncthreads();
    for (int idx = threadIdx.x; idx < 32768; idx += 256) {
        int o = idx >> 8, c = idx & 255;
        int h = c >> 5, j = c & 31;
        const float* pw = proj_w + o * 256 + h * 32;
        const float* at = As + h * 1024 + j;
        float s = 0.f;
#pragma unroll
        for (int i = 0; i < 32; i++) s = fmaf(pw[i], at[i * 32], s);
        Mfold[(long long)b * 32768 + idx] = s;
    }
}

// ----------------------------------------------------------------------------
// CSWin window attention, q-tiled: 64 threads, 4 queries/thread.
// Thread t handles tokens {t, t+64, t+128, t+192} of one window — K/V read
// from smem ONCE per key and applied to all 4 queries (4x less LDS traffic).
// ----------------------------------------------------------------------------
template <int DIR>
__global__ void __launch_bounds__(64) cswin_kernel(
    const float* __restrict__ cs, const float* __restrict__ lepe,
    float* __restrict__ outp)
{
    int win = blockIdx.x, h = blockIdx.y, b = blockIdx.z;
    int t = threadIdx.x;

    long long cb = (long long)b * 384 * NSP;
    long long ob = (long long)b * 128 * NSP;
    const float *qp, *kp, *vp, *lp;
    float* op;
    if (DIR == 0) {
        qp = cs + cb + (long long)(h * 8) * NSP;
        kp = cs + cb + (long long)(128 + h * 8) * NSP;
        vp = cs + cb + (long long)(256 + h * 8) * NSP;
        lp = vp;
        op = outp + ob + (long long)(h * 8) * NSP;
    } else {
        qp = cs + cb + (long long)(64 + h * 8) * NSP;
        kp = cs + cb + (long long)(192 + h * 8) * NSP;
        vp = cs + cb + (long long)(320 + h * 8) * NSP;
        lp = lepe + (long long)b * 64 * NSP + (long long)(h * 8) * NSP;
        op = outp + ob + (long long)(64 + h * 8) * NSP;
    }

    __shared__ float4 Ks[256][2];
    __shared__ float4 Vs[256][2];

    int nq[4];
    u64 q2[4][4];
#pragma unroll
    for (int qi = 0; qi < 4; qi++) {
        int tok = qi * 64 + t;
        int n = (DIR == 0) ? (((tok >> 2) << 6) + (win << 2) + (tok & 3))
                           : ((((win << 2) + (tok >> 6)) << 6) + (tok & 63));
        nq[qi] = n;
        float q[8], kr[8], vr[8];
#pragma unroll
        for (int d = 0; d < 8; d++) {
            q[d]  = qp[d * NSP + n] * 0.25f;    // scale = (128/8)^-0.5
            kr[d] = kp[d * NSP + n];
            vr[d] = vp[d * NSP + n];
        }
        Ks[tok][0] = make_float4(kr[0], kr[1], kr[2], kr[3]);
        Ks[tok][1] = make_float4(kr[4], kr[5], kr[6], kr[7]);
        Vs[tok][0] = make_float4(vr[0], vr[1], vr[2], vr[3]);
        Vs[tok][1] = make_float4(vr[4], vr[5], vr[6], vr[7]);
        q2[qi][0] = pack2(q[0], q[1]); q2[qi][1] = pack2(q[2], q[3]);
        q2[qi][2] = pack2(q[4], q[5]); q2[qi][3] = pack2(q[6], q[7]);
    }
    __syncthreads();

    u64 acc[4][4];
    float ssum[4];
#pragma unroll
    for (int qi = 0; qi < 4; qi++) {
        ssum[qi] = 0.f;
#pragma unroll
        for (int e = 0; e < 4; e++) acc[qi][e] = 0ull;
    }

#pragma unroll 2
    for (int j = 0; j < 256; j++) {
        ulonglong2 ka  = *(const ulonglong2*)&Ks[j][0];
        ulonglong2 kb  = *(const ulonglong2*)&Ks[j][1];
        ulonglong2 va  = *(const ulonglong2*)&Vs[j][0];
        ulonglong2 vb2 = *(const ulonglong2*)&Vs[j][1];
#pragma unroll
        for (int qi = 0; qi < 4; qi++) {
            u64 s2 = fmul2(q2[qi][0], ka.x);
            s2 = ffma2(q2[qi][1], ka.y, s2);
            s2 = ffma2(q2[qi][2], kb.x, s2);
            s2 = ffma2(q2[qi][3], kb.y, s2);
            float2 sf = unpack2(s2);
            float p = fast_exp(fminf(sf.x + sf.y, 60.f));
            ssum[qi] += p;
            u64 p2 = pack2(p, p);
            acc[qi][0] = ffma2(p2, va.x,  acc[qi][0]);
            acc[qi][1] = ffma2(p2, va.y,  acc[qi][1]);
            acc[qi][2] = ffma2(p2, vb2.x, acc[qi][2]);
            acc[qi][3] = ffma2(p2, vb2.y, acc[qi][3]);
        }
    }

#pragma unroll
    for (int qi = 0; qi < 4; qi++) {
        float inv = 1.0f / ssum[qi];
        int n = nq[qi];
#pragma unroll
        for (int dp = 0; dp < 4; dp++) {
            float2 a = unpack2(acc[qi][dp]);
            op[(dp * 2 + 0) * NSP + n] = fmaf(a.x, inv, lp[(dp * 2 + 0) * NSP + n]);
            op[(dp * 2 + 1) * NSP + n] = fmaf(a.y, inv, lp[(dp * 2 + 1) * NSP + n]);
        }
    }
}

// ----------------------------------------------------------------------------
// Launch chain
// ----------------------------------------------------------------------------
extern "C" void kernel_launch(void* const* d_in, const int* in_sizes, int n_in,
                              void* d_out, int out_size)
{
    const float* x         = (const float*)d_in[0];
    const float* ca_temp   = (const float*)d_in[1];
    const float* ca_qkv_w  = (const float*)d_in[2];
    const float* ca_proj_w = (const float*)d_in[3];
    const float* cs_qk_w   = (const float*)d_in[4];
    const float* cs_v_w    = (const float*)d_in[5];
    const float* cs_vv_w   = (const float*)d_in[6];
    const float* cs_proj_w = (const float*)d_in[8];
    float* out = (float*)d_out;

    float *qkv, *gp, *catt, *Mf, *x2, *cs, *lep, *att, *wcat;
    cudaGetSymbolAddress((void**)&qkv,  g_qkv);
    cudaGetSymbolAddress((void**)&gp,   g_gpart);
    cudaGetSymbolAddress((void**)&catt, g_catt);
    cudaGetSymbolAddress((void**)&Mf,   g_M);
    cudaGetSymbolAddress((void**)&x2,   g_x2);
    cudaGetSymbolAddress((void**)&cs,   g_cs);
    cudaGetSymbolAddress((void**)&lep,  g_lepe);
    cudaGetSymbolAddress((void**)&att,  g_att);
    cudaGetSymbolAddress((void**)&wcat, g_wcat);

    cudaFuncSetAttribute(mgemm_kernel<0>, cudaFuncAttributeMaxDynamicSharedMemorySize, MG_SMEM);
    cudaFuncSetAttribute(mgemm_kernel<1>, cudaFuncAttributeMaxDynamicSharedMemorySize, MG_SMEM);

    const long long S128 = 128LL * NSP, S384 = 384LL * NSP, S768 = 768LL * NSP, S64 = 64LL * NSP;

    // 0. weight concat for fused cswin qk|v GEMM
    concat_w_kernel<<<192, 256>>>(cs_qk_w, cs_v_w, wcat);
    // 1. qkv = ca_qkv_w @ x            (M=768, K=128)  [mma]
    mgemm_kernel<0><<<dim3(32, 6, NB), 256, MG_SMEM>>>(ca_qkv_w, x, nullptr, qkv,
                                                       768, 128, 0, S128, 0, S768);
    // 2. chunked gram + sumsq
    gram_partial_kernel<<<dim3(NCH, 128), 256>>>(qkv, gp);
    // 3. channel-attn softmax
    ca_softmax_kernel<<<128, 1024>>>(gp, ca_temp, catt);
    // 4. fold proj_w through attention
    fold_kernel<<<NB, 256>>>(catt, ca_proj_w, Mf);
    // 5. x2 = x + M_b @ V              (M=128, K=256)  [mma]
    mgemm_kernel<1><<<dim3(32, 1, NB), 256, MG_SMEM>>>(Mf, qkv + 512 * NSP, x, x2,
                                                       128, 256, 32768, S768, S128, S128);
    // 6. cs = [cs_qk_w; cs_v_w] @ x2   (M=384, K=128)  [mma]
    mgemm_kernel<0><<<dim3(32, 3, NB), 256, MG_SMEM>>>(wcat, x2, nullptr, cs,
                                                       384, 128, 0, S128, 0, S384);
    // 7. lepe_v = cs_vv_w @ v_v        (M=64, K=64)    [scalar]
    sgemm_kernel<0><<<dim3(32, 1, NB), 256>>>(cs_vv_w, cs + 320 * NSP, nullptr, lep,
                                              64, 64, 0, S384, 0, S64);
    // 8/9. CSWin attention, q-tiled (64 thr x 4 queries)
    cswin_kernel<0><<<dim3(16, 8, NB), 64>>>(cs, lep, att);
    cswin_kernel<1><<<dim3(16, 8, NB), 64>>>(cs, lep, att);
    // 10. out = x2 + cs_proj_w @ att   (M=128, K=128)  [mma]
    mgemm_kernel<1><<<dim3(32, 1, NB), 256, MG_SMEM>>>(cs_proj_w, att, x2, out,
                                                       128, 128, 0, S128, S128, S128);

    (void)in_sizes; (void)n_in; (void)out_size;
}

// round 8
// speedup vs baseline: 1.5554x; 1.1857x over previous
#include <cuda_runtime.h>
#include <cuda_bf16.h>
#include <cuda_fp16.h>
#include <cstdint>

// ----------------------------------------------------------------------------
// RecursiveBlock: channel attention + CSWin attention, b=16, DIM=128, 64x64 fp32
// R8: fp16 2-pass split GEMM (A=hi+lo fp16, B=hi fp16), 3 smem tiles ->
//     2 CTAs/SM for fill/MMA overlap. cswin q-tiled (R7).
// ----------------------------------------------------------------------------

typedef unsigned long long u64;

#define DEVFN __device__ __forceinline__

DEVFN u64 ffma2(u64 a, u64 b, u64 c) {
    u64 r; asm("fma.rn.f32x2 %0, %1, %2, %3;" : "=l"(r) : "l"(a), "l"(b), "l"(c)); return r;
}
DEVFN u64 fmul2(u64 a, u64 b) {
    u64 r; asm("mul.rn.f32x2 %0, %1, %2;" : "=l"(r) : "l"(a), "l"(b)); return r;
}
DEVFN u64 pack2(float lo, float hi) {
    u64 r; asm("mov.b64 %0, {%1, %2};" : "=l"(r) : "f"(lo), "f"(hi)); return r;
}
DEVFN float2 unpack2(u64 v) {
    float lo, hi; asm("mov.b64 {%0, %1}, %2;" : "=f"(lo), "=f"(hi) : "l"(v));
    return make_float2(lo, hi);
}

DEVFN float fast_exp(float x) {
    float t = x * 1.4426950408889634f;
    t = fmaxf(t, -126.0f);
    float fi = floorf(t);
    float f = t - fi;
    float p = 1.5403530e-4f;
    p = fmaf(p, f, 1.3333558e-3f);
    p = fmaf(p, f, 9.6181291e-3f);
    p = fmaf(p, f, 5.5504109e-2f);
    p = fmaf(p, f, 2.4022651e-1f);
    p = fmaf(p, f, 6.9314718e-1f);
    p = fmaf(p, f, 1.0f);
    return p * __int_as_float(((int)fi + 127) << 23);
}

DEVFN uint32_t smem_u32(const void* p) {
    uint32_t a;
    asm("{ .reg .u64 t; cvta.to.shared.u64 t, %1; cvt.u32.u64 %0, t; }" : "=r"(a) : "l"(p));
    return a;
}
DEVFN void ldsm_x4(uint32_t* r, uint32_t addr) {
    asm volatile("ldmatrix.sync.aligned.m8n8.x4.shared.b16 {%0,%1,%2,%3}, [%4];"
                 : "=r"(r[0]), "=r"(r[1]), "=r"(r[2]), "=r"(r[3]) : "r"(addr));
}
DEVFN void ldsm_x4_t(uint32_t* r, uint32_t addr) {
    asm volatile("ldmatrix.sync.aligned.m8n8.x4.trans.shared.b16 {%0,%1,%2,%3}, [%4];"
                 : "=r"(r[0]), "=r"(r[1]), "=r"(r[2]), "=r"(r[3]) : "r"(addr));
}
DEVFN void mma_f16(float* c, const uint32_t* a, uint32_t b0, uint32_t b1) {
    asm volatile(
        "mma.sync.aligned.m16n8k16.row.col.f32.f16.f16.f32 "
        "{%0,%1,%2,%3}, {%4,%5,%6,%7}, {%8,%9}, {%0,%1,%2,%3};"
        : "+f"(c[0]), "+f"(c[1]), "+f"(c[2]), "+f"(c[3])
        : "r"(a[0]), "r"(a[1]), "r"(a[2]), "r"(a[3]), "r"(b0), "r"(b1));
}
DEVFN uint32_t hfpack(float a, float b) {
    __half2 t = __floats2half2_rn(a, b);
    return *(uint32_t*)&t;
}

// ----------------------------------------------------------------------------
// Scratch buffers
// ----------------------------------------------------------------------------
#define NB 16
#define NSP 4096
#define NCH 8

__device__ float g_qkv [NB * 768 * NSP];
__device__ float g_gpart[128 * NCH * 1088];
__device__ float g_catt[NB * 8 * 32 * 32];
__device__ float g_M   [NB * 128 * 256];
__device__ float g_x2  [NB * 128 * NSP];
__device__ float g_cs  [NB * 384 * NSP];
__device__ float g_lepe[NB * 64 * NSP];
__device__ float g_att [NB * 128 * NSP];
__device__ float g_wcat[384 * 128];

__global__ void __launch_bounds__(256) concat_w_kernel(const float* __restrict__ qk_w,
                                                       const float* __restrict__ v_w,
                                                       float* __restrict__ wcat)
{
    int i = blockIdx.x * 256 + threadIdx.x;
    wcat[i] = (i < 256 * 128) ? qk_w[i] : v_w[i - 256 * 128];
}

// ----------------------------------------------------------------------------
// mma.sync GEMM: C[b](M,4096) = (R?) + A[b](M,K) @ B[b](K,4096)
// fp16 2-pass: A = Ah + Al (fp16 split), B = Bh (fp16). Dropped A*Bl term
// contributes ~2^-12 relative -> global rel err ~1e-4.
// smem: 3 tiles of 128 x 136 fp16 (row stride 272B, ldmatrix conflict-free).
// 102 KB smem -> 2 CTAs/SM: one block fills while the other runs MMAs.
// ----------------------------------------------------------------------------
#define RS_B 272
#define MAT_BYTES (128 * RS_B)
#define MG_SMEM (3 * MAT_BYTES)

template <int RESID>
__global__ void __launch_bounds__(256, 2) mgemm_kernel(
    const float* __restrict__ A, const float* __restrict__ B,
    const float* __restrict__ R, float* __restrict__ C,
    int M, int K, long long sA, long long sB, long long sR, long long sC)
{
    extern __shared__ char smem[];
    char* pAh = smem;
    char* pAl = smem + MAT_BYTES;
    char* pBh = smem + 2 * MAT_BYTES;
    uint32_t aAh = smem_u32(pAh), aAl = smem_u32(pAl);
    uint32_t aBh = smem_u32(pBh);

    int tid = threadIdx.x, wid = tid >> 5, lane = tid & 31;
    int nBase = blockIdx.x * 128;
    int mBase = blockIdx.y * 128;
    int bz = blockIdx.z;
    A += bz * sA; B += bz * sB; C += bz * sC;
    if (RESID) R += bz * sR;

    int mw = (wid >> 1) * 32;
    int nw = (wid & 1) * 64;

    float acc[2][8][4];
#pragma unroll
    for (int t = 0; t < 2; t++)
#pragma unroll
        for (int n = 0; n < 8; n++)
#pragma unroll
            for (int e = 0; e < 4; e++) acc[t][n][e] = 0.f;

    int lrow = lane & 7;
    int lm8  = (lane >> 3) & 1;
    int lk8  = lane >> 4;

    for (int k0 = 0; k0 < K; k0 += 128) {
        // ---- fill A: [m][k] fp16 hi + lo ----
        for (int idx = tid; idx < 4096; idx += 256) {
            int m = idx >> 5, kq = (idx & 31) << 2;
            float4 v = *(const float4*)&A[(long long)(mBase + m) * K + k0 + kq];
            __half hx = __float2half_rn(v.x), hy = __float2half_rn(v.y);
            __half hz = __float2half_rn(v.z), hw = __float2half_rn(v.w);
            float fx = __half2float(hx), fy = __half2float(hy);
            float fz = __half2float(hz), fw = __half2float(hw);
            int off = m * RS_B + kq * 2;
            *(uint2*)(pAh + off) = make_uint2(hfpack(fx, fy), hfpack(fz, fw));
            *(uint2*)(pAl + off) = make_uint2(hfpack(v.x - fx, v.y - fy),
                                              hfpack(v.z - fz, v.w - fw));
        }
        // ---- fill B: [k][n] fp16 hi only ----
        for (int idx = tid; idx < 4096; idx += 256) {
            int k = idx >> 5, nq = (idx & 31) << 2;
            float4 v = *(const float4*)&B[(long long)(k0 + k) * 4096 + nBase + nq];
            int off = k * RS_B + nq * 2;
            *(uint2*)(pBh + off) = make_uint2(hfpack(v.x, v.y), hfpack(v.z, v.w));
        }
        __syncthreads();

#pragma unroll
        for (int ks = 0; ks < 8; ks++) {
            uint32_t ah[2][4], al[2][4];
#pragma unroll
            for (int t = 0; t < 2; t++) {
                int m = mw + t * 16 + lrow + lm8 * 8;
                int k = ks * 16 + lk8 * 8;
                uint32_t off = (uint32_t)(m * RS_B + k * 2);
                ldsm_x4(ah[t], aAh + off);
                ldsm_x4(al[t], aAl + off);
            }
#pragma unroll
            for (int np = 0; np < 4; np++) {
                int k = ks * 16 + lm8 * 8 + lrow;
                int n = nw + np * 16 + lk8 * 8;
                uint32_t off = (uint32_t)(k * RS_B + n * 2);
                uint32_t bh[4];
                ldsm_x4_t(bh, aBh + off);
#pragma unroll
                for (int t = 0; t < 2; t++) {
                    mma_f16(acc[t][np * 2],     ah[t], bh[0], bh[1]);
                    mma_f16(acc[t][np * 2],     al[t], bh[0], bh[1]);
                    mma_f16(acc[t][np * 2 + 1], ah[t], bh[2], bh[3]);
                    mma_f16(acc[t][np * 2 + 1], al[t], bh[2], bh[3]);
                }
            }
        }
        __syncthreads();
    }

    int gid = lane >> 2, tig = lane & 3;
#pragma unroll
    for (int t = 0; t < 2; t++) {
#pragma unroll
        for (int nt = 0; nt < 8; nt++) {
            int row = mBase + mw + t * 16 + gid;
            int col = nBase + nw + nt * 8 + tig * 2;
            long long o0 = (long long)row * 4096 + col;
            long long o1 = (long long)(row + 8) * 4096 + col;
            float2 v0 = make_float2(acc[t][nt][0], acc[t][nt][1]);
            float2 v1 = make_float2(acc[t][nt][2], acc[t][nt][3]);
            if (RESID) {
                float2 r0 = *(const float2*)&R[o0];
                float2 r1 = *(const float2*)&R[o1];
                v0.x += r0.x; v0.y += r0.y; v1.x += r1.x; v1.y += r1.y;
            }
            *(float2*)&C[o0] = v0;
            *(float2*)&C[o1] = v1;
        }
    }
}

// ----------------------------------------------------------------------------
// Scalar SGEMM (lepe)
// ----------------------------------------------------------------------------
template <int RESID>
__global__ void __launch_bounds__(256, 2) sgemm_kernel(
    const float* __restrict__ A, const float* __restrict__ B,
    const float* __restrict__ R, float* __restrict__ C,
    int M, int K, long long sA, long long sB, long long sR, long long sC)
{
    const int N = 4096;
    int bz = blockIdx.z;
    A += bz * sA; B += bz * sB; C += bz * sC;
    if (RESID) R += bz * sR;

    int mBase = blockIdx.y * 128;
    int nBase = blockIdx.x * 128;

    __shared__ __align__(16) float As[2][8][128];
    __shared__ __align__(16) float Bs[2][8][128];

    int tid  = threadIdx.x;
    int aRow = tid >> 1;
    int aCol = (tid & 1) << 2;
    int bRow = tid >> 5;
    int bCol = (tid & 31) << 2;
    int tx = tid & 15, ty = tid >> 4;

    u64 acc[8][4];
#pragma unroll
    for (int i = 0; i < 8; i++)
#pragma unroll
        for (int j = 0; j < 4; j++) acc[i][j] = 0ull;

    const bool aValid = (mBase + aRow) < M;
    const float* Aptr = A + (long long)(mBase + aRow) * K + aCol;
    const float* Bptr = B + (long long)bRow * N + nBase + bCol;

    const int ntiles = K >> 3;

    float4 av = make_float4(0.f, 0.f, 0.f, 0.f);
    if (aValid) av = *(const float4*)(Aptr);
    float4 bv = *(const float4*)(Bptr);

    for (int i = 0; i < ntiles; i++) {
        int p = i & 1;
        As[p][aCol + 0][aRow] = av.x;
        As[p][aCol + 1][aRow] = av.y;
        As[p][aCol + 2][aRow] = av.z;
        As[p][aCol + 3][aRow] = av.w;
        *(float4*)&Bs[p][bRow][bCol] = bv;
        __syncthreads();

        if (i + 1 < ntiles) {
            av = make_float4(0.f, 0.f, 0.f, 0.f);
            if (aValid) av = *(const float4*)(Aptr + (i + 1) * 8);
            bv = *(const float4*)(Bptr + (long long)(i + 1) * 8 * N);
        }

#pragma unroll
        for (int kk = 0; kk < 8; kk++) {
            float4 aLo = *(float4*)&As[p][kk][ty * 4];
            float4 aHi = *(float4*)&As[p][kk][64 + ty * 4];
            ulonglong2 bl = *(const ulonglong2*)&Bs[p][kk][tx * 4];
            ulonglong2 bh = *(const ulonglong2*)&Bs[p][kk][64 + tx * 4];
            u64 b2[4] = {bl.x, bl.y, bh.x, bh.y};
            float a[8] = {aLo.x, aLo.y, aLo.z, aLo.w, aHi.x, aHi.y, aHi.z, aHi.w};
#pragma unroll
            for (int ii = 0; ii < 8; ii++) {
                u64 ad = pack2(a[ii], a[ii]);
#pragma unroll
                for (int j = 0; j < 4; j++) acc[ii][j] = ffma2(ad, b2[j], acc[ii][j]);
            }
        }
    }

#pragma unroll
    for (int i = 0; i < 8; i++) {
        int m = mBase + ((i < 4) ? (ty * 4 + i) : (64 + ty * 4 + (i - 4)));
        if (m < M) {
            long long rowoff = (long long)m * N + nBase;
#pragma unroll
            for (int half = 0; half < 2; half++) {
                int col = (half == 0) ? (tx * 4) : (64 + tx * 4);
                float2 p0 = unpack2(acc[i][half * 2 + 0]);
                float2 p1 = unpack2(acc[i][half * 2 + 1]);
                float4 v = make_float4(p0.x, p0.y, p1.x, p1.y);
                if (RESID) {
                    float4 rv = *(const float4*)&R[rowoff + col];
                    v.x += rv.x; v.y += rv.y; v.z += rv.z; v.w += rv.w;
                }
                *(float4*)&C[rowoff + col] = v;
            }
        }
    }
}

// ----------------------------------------------------------------------------
// Chunked Gram + fused sum-of-squares
// ----------------------------------------------------------------------------
__global__ void __launch_bounds__(256) gram_partial_kernel(const float* __restrict__ qkv,
                                                           float* __restrict__ gpart)
{
    int chunk = blockIdx.x;
    int bh = blockIdx.y;
    int b = bh >> 3, h = bh & 7;
    const float* Q  = qkv + ((long long)b * 768 + h * 32) * NSP;
    const float* Kp = qkv + ((long long)b * 768 + 256 + h * 32) * NSP;

    __shared__ float Qs[32 * 68];
    __shared__ float Ks[32 * 68];

    int tx = threadIdx.x & 15, ty = threadIdx.x >> 4;
    int r4 = threadIdx.x >> 2;
    int quad = threadIdx.x & 3;
    float a00 = 0.f, a01 = 0.f, a10 = 0.f, a11 = 0.f;
    float ssq = 0.f;

    int c_beg = chunk * (NSP / NCH);
    for (int c0 = c_beg; c0 < c_beg + (NSP / NCH); c0 += 64) {
        __syncthreads();
        for (int l = threadIdx.x; l < 2048; l += 256) {
            int r = l >> 6, cc = l & 63;
            Qs[r * 68 + cc] = Q[(long long)r * NSP + c0 + cc];
            Ks[r * 68 + cc] = Kp[(long long)r * NSP + c0 + cc];
        }
        __syncthreads();
#pragma unroll
        for (int tt = 0; tt < 64; tt += 4) {
            float4 q0 = *(float4*)&Qs[ty * 68 + tt];
            float4 q1 = *(float4*)&Qs[(ty + 16) * 68 + tt];
            float4 k0 = *(float4*)&Ks[tx * 68 + tt];
            float4 k1 = *(float4*)&Ks[(tx + 16) * 68 + tt];
            a00 = fmaf(q0.x, k0.x, fmaf(q0.y, k0.y, fmaf(q0.z, k0.z, fmaf(q0.w, k0.w, a00))));
            a01 = fmaf(q0.x, k1.x, fmaf(q0.y, k1.y, fmaf(q0.z, k1.z, fmaf(q0.w, k1.w, a01))));
            a10 = fmaf(q1.x, k0.x, fmaf(q1.y, k0.y, fmaf(q1.z, k0.z, fmaf(q1.w, k0.w, a10))));
            a11 = fmaf(q1.x, k1.x, fmaf(q1.y, k1.y, fmaf(q1.z, k1.z, fmaf(q1.w, k1.w, a11))));
        }
        const float* src = (r4 < 32) ? &Qs[r4 * 68] : &Ks[(r4 - 32) * 68];
#pragma unroll
        for (int e = 0; e < 16; e++) {
            float v = src[quad * 16 + e];
            ssq = fmaf(v, v, ssq);
        }
    }
    ssq += __shfl_xor_sync(0xffffffffu, ssq, 1);
    ssq += __shfl_xor_sync(0xffffffffu, ssq, 2);

    float* out = gpart + ((long long)bh * NCH + chunk) * 1088;
    out[ty * 32 + tx]               = a00;
    out[ty * 32 + tx + 16]          = a01;
    out[(ty + 16) * 32 + tx]        = a10;
    out[(ty + 16) * 32 + tx + 16]   = a11;
    if (quad == 0) out[1024 + r4] = ssq;
}

__global__ void __launch_bounds__(1024) ca_softmax_kernel(
    const float* __restrict__ gpart, const float* __restrict__ temp,
    float* __restrict__ attn)
{
    int bh = blockIdx.x;
    int h = bh & 7;
    int t = threadIdx.x;
    const float* base = gpart + (long long)bh * NCH * 1088;

    __shared__ float ninv[64];
    if (t < 64) {
        float ss = 0.f;
#pragma unroll
        for (int c = 0; c < NCH; c++) ss += base[c * 1088 + 1024 + t];
        ninv[t] = 1.0f / fmaxf(sqrtf(ss), 1e-12f);
    }

    int i = t >> 5, j = t & 31;
    float g = 0.f;
#pragma unroll
    for (int c = 0; c < NCH; c++) g += base[c * 1088 + i * 32 + j];
    __syncthreads();

    float l = g * ninv[i] * ninv[32 + j] * temp[h];
    float m = l;
#pragma unroll
    for (int off = 16; off > 0; off >>= 1) m = fmaxf(m, __shfl_xor_sync(0xffffffffu, m, off));
    float p = fast_exp(l - m);
    float s = p;
#pragma unroll
    for (int off = 16; off > 0; off >>= 1) s += __shfl_xor_sync(0xffffffffu, s, off);
    attn[(long long)bh * 1024 + i * 32 + j] = p / s;
}

__global__ void __launch_bounds__(256) fold_kernel(const float* __restrict__ attn,
                                                   const float* __restrict__ proj_w,
                                                   float* __restrict__ Mfold)
{
    int b = blockIdx.x;
    __shared__ float As[8192];
    for (int l = threadIdx.x; l < 8192; l += 256) As[l] = attn[(long long)b * 8192 + l];
    __syncthreads();
    for (int idx = threadIdx.x; idx < 32768; idx += 256) {
        int o = idx >> 8, c = idx & 255;
        int h = c >> 5, j = c & 31;
        const float* pw = proj_w + o * 256 + h * 32;
        const float* at = As + h * 1024 + j;
        float s = 0.f;
#pragma unroll
        for (int i = 0; i < 32; i++) s = fmaf(pw[i], at[i * 32], s);
        Mfold[(long long)b * 32768 + idx] = s;
    }
}

// ----------------------------------------------------------------------------
// CSWin window attention, q-tiled (R7)
// ----------------------------------------------------------------------------
template <int DIR>
__global__ void __launch_bounds__(64) cswin_kernel(
    const float* __restrict__ cs, const float* __restrict__ lepe,
    float* __restrict__ outp)
{
    int win = blockIdx.x, h = blockIdx.y, b = blockIdx.z;
    int t = threadIdx.x;

    long long cb = (long long)b * 384 * NSP;
    long long ob = (long long)b * 128 * NSP;
    const float *qp, *kp, *vp, *lp;
    float* op;
    if (DIR == 0) {
        qp = cs + cb + (long long)(h * 8) * NSP;
        kp = cs + cb + (long long)(128 + h * 8) * NSP;
        vp = cs + cb + (long long)(256 + h * 8) * NSP;
        lp = vp;
        op = outp + ob + (long long)(h * 8) * NSP;
    } else {
        qp = cs + cb + (long long)(64 + h * 8) * NSP;
        kp = cs + cb + (long long)(192 + h * 8) * NSP;
        vp = cs + cb + (long long)(320 + h * 8) * NSP;
        lp = lepe + (long long)b * 64 * NSP + (long long)(h * 8) * NSP;
        op = outp + ob + (long long)(64 + h * 8) * NSP;
    }

    __shared__ float4 Ks[256][2];
    __shared__ float4 Vs[256][2];

    int nq[4];
    u64 q2[4][4];
#pragma unroll
    for (int qi = 0; qi < 4; qi++) {
        int tok = qi * 64 + t;
        int n = (DIR == 0) ? (((tok >> 2) << 6) + (win << 2) + (tok & 3))
                           : ((((win << 2) + (tok >> 6)) << 6) + (tok & 63));
        nq[qi] = n;
        float q[8], kr[8], vr[8];
#pragma unroll
        for (int d = 0; d < 8; d++) {
            q[d]  = qp[d * NSP + n] * 0.25f;
            kr[d] = kp[d * NSP + n];
            vr[d] = vp[d * NSP + n];
        }
        Ks[tok][0] = make_float4(kr[0], kr[1], kr[2], kr[3]);
        Ks[tok][1] = make_float4(kr[4], kr[5], kr[6], kr[7]);
        Vs[tok][0] = make_float4(vr[0], vr[1], vr[2], vr[3]);
        Vs[tok][1] = make_float4(vr[4], vr[5], vr[6], vr[7]);
        q2[qi][0] = pack2(q[0], q[1]); q2[qi][1] = pack2(q[2], q[3]);
        q2[qi][2] = pack2(q[4], q[5]); q2[qi][3] = pack2(q[6], q[7]);
    }
    __syncthreads();

    u64 acc[4][4];
    float ssum[4];
#pragma unroll
    for (int qi = 0; qi < 4; qi++) {
        ssum[qi] = 0.f;
#pragma unroll
        for (int e = 0; e < 4; e++) acc[qi][e] = 0ull;
    }

#pragma unroll 2
    for (int j = 0; j < 256; j++) {
        ulonglong2 ka  = *(const ulonglong2*)&Ks[j][0];
        ulonglong2 kb  = *(const ulonglong2*)&Ks[j][1];
        ulonglong2 va  = *(const ulonglong2*)&Vs[j][0];
        ulonglong2 vb2 = *(const ulonglong2*)&Vs[j][1];
#pragma unroll
        for (int qi = 0; qi < 4; qi++) {
            u64 s2 = fmul2(q2[qi][0], ka.x);
            s2 = ffma2(q2[qi][1], ka.y, s2);
            s2 = ffma2(q2[qi][2], kb.x, s2);
            s2 = ffma2(q2[qi][3], kb.y, s2);
            float2 sf = unpack2(s2);
            float p = fast_exp(fminf(sf.x + sf.y, 60.f));
            ssum[qi] += p;
            u64 p2 = pack2(p, p);
            acc[qi][0] = ffma2(p2, va.x,  acc[qi][0]);
            acc[qi][1] = ffma2(p2, va.y,  acc[qi][1]);
            acc[qi][2] = ffma2(p2, vb2.x, acc[qi][2]);
            acc[qi][3] = ffma2(p2, vb2.y, acc[qi][3]);
        }
    }

#pragma unroll
    for (int qi = 0; qi < 4; qi++) {
        float inv = 1.0f / ssum[qi];
        int n = nq[qi];
#pragma unroll
        for (int dp = 0; dp < 4; dp++) {
            float2 a = unpack2(acc[qi][dp]);
            op[(dp * 2 + 0) * NSP + n] = fmaf(a.x, inv, lp[(dp * 2 + 0) * NSP + n]);
            op[(dp * 2 + 1) * NSP + n] = fmaf(a.y, inv, lp[(dp * 2 + 1) * NSP + n]);
        }
    }
}

// ----------------------------------------------------------------------------
// Launch chain
// ----------------------------------------------------------------------------
extern "C" void kernel_launch(void* const* d_in, const int* in_sizes, int n_in,
                              void* d_out, int out_size)
{
    const float* x         = (const float*)d_in[0];
    const float* ca_temp   = (const float*)d_in[1];
    const float* ca_qkv_w  = (const float*)d_in[2];
    const float* ca_proj_w = (const float*)d_in[3];
    const float* cs_qk_w   = (const float*)d_in[4];
    const float* cs_v_w    = (const float*)d_in[5];
    const float* cs_vv_w   = (const float*)d_in[6];
    const float* cs_proj_w = (const float*)d_in[8];
    float* out = (float*)d_out;

    float *qkv, *gp, *catt, *Mf, *x2, *cs, *lep, *att, *wcat;
    cudaGetSymbolAddress((void**)&qkv,  g_qkv);
    cudaGetSymbolAddress((void**)&gp,   g_gpart);
    cudaGetSymbolAddress((void**)&catt, g_catt);
    cudaGetSymbolAddress((void**)&Mf,   g_M);
    cudaGetSymbolAddress((void**)&x2,   g_x2);
    cudaGetSymbolAddress((void**)&cs,   g_cs);
    cudaGetSymbolAddress((void**)&lep,  g_lepe);
    cudaGetSymbolAddress((void**)&att,  g_att);
    cudaGetSymbolAddress((void**)&wcat, g_wcat);

    cudaFuncSetAttribute(mgemm_kernel<0>, cudaFuncAttributeMaxDynamicSharedMemorySize, MG_SMEM);
    cudaFuncSetAttribute(mgemm_kernel<1>, cudaFuncAttributeMaxDynamicSharedMemorySize, MG_SMEM);

    const long long S128 = 128LL * NSP, S384 = 384LL * NSP, S768 = 768LL * NSP, S64 = 64LL * NSP;

    // 0. weight concat for fused cswin qk|v GEMM
    concat_w_kernel<<<192, 256>>>(cs_qk_w, cs_v_w, wcat);
    // 1. qkv = ca_qkv_w @ x            (M=768, K=128)  [mma fp16 2-pass]
    mgemm_kernel<0><<<dim3(32, 6, NB), 256, MG_SMEM>>>(ca_qkv_w, x, nullptr, qkv,
                                                       768, 128, 0, S128, 0, S768);
    // 2. chunked gram + sumsq
    gram_partial_kernel<<<dim3(NCH, 128), 256>>>(qkv, gp);
    // 3. channel-attn softmax
    ca_softmax_kernel<<<128, 1024>>>(gp, ca_temp, catt);
    // 4. fold proj_w through attention
    fold_kernel<<<NB, 256>>>(catt, ca_proj_w, Mf);
    // 5. x2 = x + M_b @ V              (M=128, K=256)  [mma]
    mgemm_kernel<1><<<dim3(32, 1, NB), 256, MG_SMEM>>>(Mf, qkv + 512 * NSP, x, x2,
                                                       128, 256, 32768, S768, S128, S128);
    // 6. cs = [cs_qk_w; cs_v_w] @ x2   (M=384, K=128)  [mma]
    mgemm_kernel<0><<<dim3(32, 3, NB), 256, MG_SMEM>>>(wcat, x2, nullptr, cs,
                                                       384, 128, 0, S128, 0, S384);
    // 7. lepe_v = cs_vv_w @ v_v        (M=64, K=64)    [scalar]
    sgemm_kernel<0><<<dim3(32, 1, NB), 256>>>(cs_vv_w, cs + 320 * NSP, nullptr, lep,
                                              64, 64, 0, S384, 0, S64);
    // 8/9. CSWin attention, q-tiled
    cswin_kernel<0><<<dim3(16, 8, NB), 64>>>(cs, lep, att);
    cswin_kernel<1><<<dim3(16, 8, NB), 64>>>(cs, lep, att);
    // 10. out = x2 + cs_proj_w @ att   (M=128, K=128)  [mma]
    mgemm_kernel<1><<<dim3(32, 1, NB), 256, MG_SMEM>>>(cs_proj_w, att, x2, out,
                                                       128, 128, 0, S128, S128, S128);

    (void)in_sizes; (void)n_in; (void)out_size;
}

// round 9
// speedup vs baseline: 1.6784x; 1.0791x over previous
#include <cuda_runtime.h>
#include <cuda_bf16.h>
#include <cuda_fp16.h>
#include <cstdint>

// ----------------------------------------------------------------------------
// RecursiveBlock: channel attention + CSWin attention, b=16, DIM=128, 64x64 fp32
// R9: single-pass fp16 GEMM (A=hi, B=hi, fp32 accum) — R8 measured that each
// dropped correction term costs ~7e-5 network rel_err, so 1-pass ~1.5e-4.
// ----------------------------------------------------------------------------

typedef unsigned long long u64;

#define DEVFN __device__ __forceinline__

DEVFN u64 ffma2(u64 a, u64 b, u64 c) {
    u64 r; asm("fma.rn.f32x2 %0, %1, %2, %3;" : "=l"(r) : "l"(a), "l"(b), "l"(c)); return r;
}
DEVFN u64 fmul2(u64 a, u64 b) {
    u64 r; asm("mul.rn.f32x2 %0, %1, %2;" : "=l"(r) : "l"(a), "l"(b)); return r;
}
DEVFN u64 pack2(float lo, float hi) {
    u64 r; asm("mov.b64 %0, {%1, %2};" : "=l"(r) : "f"(lo), "f"(hi)); return r;
}
DEVFN float2 unpack2(u64 v) {
    float lo, hi; asm("mov.b64 {%0, %1}, %2;" : "=f"(lo), "=f"(hi) : "l"(v));
    return make_float2(lo, hi);
}

DEVFN float fast_exp(float x) {
    float t = x * 1.4426950408889634f;
    t = fmaxf(t, -126.0f);
    float fi = floorf(t);
    float f = t - fi;
    float p = 1.5403530e-4f;
    p = fmaf(p, f, 1.3333558e-3f);
    p = fmaf(p, f, 9.6181291e-3f);
    p = fmaf(p, f, 5.5504109e-2f);
    p = fmaf(p, f, 2.4022651e-1f);
    p = fmaf(p, f, 6.9314718e-1f);
    p = fmaf(p, f, 1.0f);
    return p * __int_as_float(((int)fi + 127) << 23);
}

DEVFN uint32_t smem_u32(const void* p) {
    uint32_t a;
    asm("{ .reg .u64 t; cvta.to.shared.u64 t, %1; cvt.u32.u64 %0, t; }" : "=r"(a) : "l"(p));
    return a;
}
DEVFN void ldsm_x4(uint32_t* r, uint32_t addr) {
    asm volatile("ldmatrix.sync.aligned.m8n8.x4.shared.b16 {%0,%1,%2,%3}, [%4];"
                 : "=r"(r[0]), "=r"(r[1]), "=r"(r[2]), "=r"(r[3]) : "r"(addr));
}
DEVFN void ldsm_x4_t(uint32_t* r, uint32_t addr) {
    asm volatile("ldmatrix.sync.aligned.m8n8.x4.trans.shared.b16 {%0,%1,%2,%3}, [%4];"
                 : "=r"(r[0]), "=r"(r[1]), "=r"(r[2]), "=r"(r[3]) : "r"(addr));
}
DEVFN void mma_f16(float* c, const uint32_t* a, uint32_t b0, uint32_t b1) {
    asm volatile(
        "mma.sync.aligned.m16n8k16.row.col.f32.f16.f16.f32 "
        "{%0,%1,%2,%3}, {%4,%5,%6,%7}, {%8,%9}, {%0,%1,%2,%3};"
        : "+f"(c[0]), "+f"(c[1]), "+f"(c[2]), "+f"(c[3])
        : "r"(a[0]), "r"(a[1]), "r"(a[2]), "r"(a[3]), "r"(b0), "r"(b1));
}
DEVFN uint32_t hfpack(float a, float b) {
    __half2 t = __floats2half2_rn(a, b);
    return *(uint32_t*)&t;
}

// ----------------------------------------------------------------------------
// Scratch buffers
// ----------------------------------------------------------------------------
#define NB 16
#define NSP 4096
#define NCH 8

__device__ float g_qkv [NB * 768 * NSP];
__device__ float g_gpart[128 * NCH * 1088];
__device__ float g_catt[NB * 8 * 32 * 32];
__device__ float g_M   [NB * 128 * 256];
__device__ float g_x2  [NB * 128 * NSP];
__device__ float g_cs  [NB * 384 * NSP];
__device__ float g_lepe[NB * 64 * NSP];
__device__ float g_att [NB * 128 * NSP];
__device__ float g_wcat[384 * 128];

__global__ void __launch_bounds__(256) concat_w_kernel(const float* __restrict__ qk_w,
                                                       const float* __restrict__ v_w,
                                                       float* __restrict__ wcat)
{
    int i = blockIdx.x * 256 + threadIdx.x;
    wcat[i] = (i < 256 * 128) ? qk_w[i] : v_w[i - 256 * 128];
}

// ----------------------------------------------------------------------------
// mma.sync GEMM: C[b](M,4096) = (R?) + A[b](M,K) @ B[b](K,4096)
// Single-pass fp16 (A=hi, B=hi), fp32 accum. Network rel err ~1.5e-4
// (empirically calibrated: each dropped correction term costs ~7e-5).
// smem: 2 tiles of 128 x 136 fp16 (68 KB) -> 2 CTAs/SM.
// ----------------------------------------------------------------------------
#define RS_B 272
#define MAT_BYTES (128 * RS_B)
#define MG_SMEM (2 * MAT_BYTES)

template <int RESID>
__global__ void __launch_bounds__(256, 2) mgemm_kernel(
    const float* __restrict__ A, const float* __restrict__ B,
    const float* __restrict__ R, float* __restrict__ C,
    int M, int K, long long sA, long long sB, long long sR, long long sC)
{
    extern __shared__ char smem[];
    char* pAh = smem;
    char* pBh = smem + MAT_BYTES;
    uint32_t aAh = smem_u32(pAh);
    uint32_t aBh = smem_u32(pBh);

    int tid = threadIdx.x, wid = tid >> 5, lane = tid & 31;
    int nBase = blockIdx.x * 128;
    int mBase = blockIdx.y * 128;
    int bz = blockIdx.z;
    A += bz * sA; B += bz * sB; C += bz * sC;
    if (RESID) R += bz * sR;

    int mw = (wid >> 1) * 32;
    int nw = (wid & 1) * 64;

    float acc[2][8][4];
#pragma unroll
    for (int t = 0; t < 2; t++)
#pragma unroll
        for (int n = 0; n < 8; n++)
#pragma unroll
            for (int e = 0; e < 4; e++) acc[t][n][e] = 0.f;

    int lrow = lane & 7;
    int lm8  = (lane >> 3) & 1;
    int lk8  = lane >> 4;

    for (int k0 = 0; k0 < K; k0 += 128) {
        // ---- fill A: [m][k] fp16 ----
        for (int idx = tid; idx < 4096; idx += 256) {
            int m = idx >> 5, kq = (idx & 31) << 2;
            float4 v = *(const float4*)&A[(long long)(mBase + m) * K + k0 + kq];
            int off = m * RS_B + kq * 2;
            *(uint2*)(pAh + off) = make_uint2(hfpack(v.x, v.y), hfpack(v.z, v.w));
        }
        // ---- fill B: [k][n] fp16 ----
        for (int idx = tid; idx < 4096; idx += 256) {
            int k = idx >> 5, nq = (idx & 31) << 2;
            float4 v = *(const float4*)&B[(long long)(k0 + k) * 4096 + nBase + nq];
            int off = k * RS_B + nq * 2;
            *(uint2*)(pBh + off) = make_uint2(hfpack(v.x, v.y), hfpack(v.z, v.w));
        }
        __syncthreads();

#pragma unroll
        for (int ks = 0; ks < 8; ks++) {
            uint32_t ah[2][4];
#pragma unroll
            for (int t = 0; t < 2; t++) {
                int m = mw + t * 16 + lrow + lm8 * 8;
                int k = ks * 16 + lk8 * 8;
                ldsm_x4(ah[t], aAh + (uint32_t)(m * RS_B + k * 2));
            }
#pragma unroll
            for (int np = 0; np < 4; np++) {
                int k = ks * 16 + lm8 * 8 + lrow;
                int n = nw + np * 16 + lk8 * 8;
                uint32_t bh[4];
                ldsm_x4_t(bh, aBh + (uint32_t)(k * RS_B + n * 2));
#pragma unroll
                for (int t = 0; t < 2; t++) {
                    mma_f16(acc[t][np * 2],     ah[t], bh[0], bh[1]);
                    mma_f16(acc[t][np * 2 + 1], ah[t], bh[2], bh[3]);
                }
            }
        }
        __syncthreads();
    }

    int gid = lane >> 2, tig = lane & 3;
#pragma unroll
    for (int t = 0; t < 2; t++) {
#pragma unroll
        for (int nt = 0; nt < 8; nt++) {
            int row = mBase + mw + t * 16 + gid;
            int col = nBase + nw + nt * 8 + tig * 2;
            long long o0 = (long long)row * 4096 + col;
            long long o1 = (long long)(row + 8) * 4096 + col;
            float2 v0 = make_float2(acc[t][nt][0], acc[t][nt][1]);
            float2 v1 = make_float2(acc[t][nt][2], acc[t][nt][3]);
            if (RESID) {
                float2 r0 = *(const float2*)&R[o0];
                float2 r1 = *(const float2*)&R[o1];
                v0.x += r0.x; v0.y += r0.y; v1.x += r1.x; v1.y += r1.y;
            }
            *(float2*)&C[o0] = v0;
            *(float2*)&C[o1] = v1;
        }
    }
}

// ----------------------------------------------------------------------------
// Scalar SGEMM (lepe)
// ----------------------------------------------------------------------------
template <int RESID>
__global__ void __launch_bounds__(256, 2) sgemm_kernel(
    const float* __restrict__ A, const float* __restrict__ B,
    const float* __restrict__ R, float* __restrict__ C,
    int M, int K, long long sA, long long sB, long long sR, long long sC)
{
    const int N = 4096;
    int bz = blockIdx.z;
    A += bz * sA; B += bz * sB; C += bz * sC;
    if (RESID) R += bz * sR;

    int mBase = blockIdx.y * 128;
    int nBase = blockIdx.x * 128;

    __shared__ __align__(16) float As[2][8][128];
    __shared__ __align__(16) float Bs[2][8][128];

    int tid  = threadIdx.x;
    int aRow = tid >> 1;
    int aCol = (tid & 1) << 2;
    int bRow = tid >> 5;
    int bCol = (tid & 31) << 2;
    int tx = tid & 15, ty = tid >> 4;

    u64 acc[8][4];
#pragma unroll
    for (int i = 0; i < 8; i++)
#pragma unroll
        for (int j = 0; j < 4; j++) acc[i][j] = 0ull;

    const bool aValid = (mBase + aRow) < M;
    const float* Aptr = A + (long long)(mBase + aRow) * K + aCol;
    const float* Bptr = B + (long long)bRow * N + nBase + bCol;

    const int ntiles = K >> 3;

    float4 av = make_float4(0.f, 0.f, 0.f, 0.f);
    if (aValid) av = *(const float4*)(Aptr);
    float4 bv = *(const float4*)(Bptr);

    for (int i = 0; i < ntiles; i++) {
        int p = i & 1;
        As[p][aCol + 0][aRow] = av.x;
        As[p][aCol + 1][aRow] = av.y;
        As[p][aCol + 2][aRow] = av.z;
        As[p][aCol + 3][aRow] = av.w;
        *(float4*)&Bs[p][bRow][bCol] = bv;
        __syncthreads();

        if (i + 1 < ntiles) {
            av = make_float4(0.f, 0.f, 0.f, 0.f);
            if (aValid) av = *(const float4*)(Aptr + (i + 1) * 8);
            bv = *(const float4*)(Bptr + (long long)(i + 1) * 8 * N);
        }

#pragma unroll
        for (int kk = 0; kk < 8; kk++) {
            float4 aLo = *(float4*)&As[p][kk][ty * 4];
            float4 aHi = *(float4*)&As[p][kk][64 + ty * 4];
            ulonglong2 bl = *(const ulonglong2*)&Bs[p][kk][tx * 4];
            ulonglong2 bh = *(const ulonglong2*)&Bs[p][kk][64 + tx * 4];
            u64 b2[4] = {bl.x, bl.y, bh.x, bh.y};
            float a[8] = {aLo.x, aLo.y, aLo.z, aLo.w, aHi.x, aHi.y, aHi.z, aHi.w};
#pragma unroll
            for (int ii = 0; ii < 8; ii++) {
                u64 ad = pack2(a[ii], a[ii]);
#pragma unroll
                for (int j = 0; j < 4; j++) acc[ii][j] = ffma2(ad, b2[j], acc[ii][j]);
            }
        }
    }

#pragma unroll
    for (int i = 0; i < 8; i++) {
        int m = mBase + ((i < 4) ? (ty * 4 + i) : (64 + ty * 4 + (i - 4)));
        if (m < M) {
            long long rowoff = (long long)m * N + nBase;
#pragma unroll
            for (int half = 0; half < 2; half++) {
                int col = (half == 0) ? (tx * 4) : (64 + tx * 4);
                float2 p0 = unpack2(acc[i][half * 2 + 0]);
                float2 p1 = unpack2(acc[i][half * 2 + 1]);
                float4 v = make_float4(p0.x, p0.y, p1.x, p1.y);
                if (RESID) {
                    float4 rv = *(const float4*)&R[rowoff + col];
                    v.x += rv.x; v.y += rv.y; v.z += rv.z; v.w += rv.w;
                }
                *(float4*)&C[rowoff + col] = v;
            }
        }
    }
}

// ----------------------------------------------------------------------------
// Chunked Gram + fused sum-of-squares
// ----------------------------------------------------------------------------
__global__ void __launch_bounds__(256) gram_partial_kernel(const float* __restrict__ qkv,
                                                           float* __restrict__ gpart)
{
    int chunk = blockIdx.x;
    int bh = blockIdx.y;
    int b = bh >> 3, h = bh & 7;
    const float* Q  = qkv + ((long long)b * 768 + h * 32) * NSP;
    const float* Kp = qkv + ((long long)b * 768 + 256 + h * 32) * NSP;

    __shared__ float Qs[32 * 68];
    __shared__ float Ks[32 * 68];

    int tx = threadIdx.x & 15, ty = threadIdx.x >> 4;
    int r4 = threadIdx.x >> 2;
    int quad = threadIdx.x & 3;
    float a00 = 0.f, a01 = 0.f, a10 = 0.f, a11 = 0.f;
    float ssq = 0.f;

    int c_beg = chunk * (NSP / NCH);
    for (int c0 = c_beg; c0 < c_beg + (NSP / NCH); c0 += 64) {
        __syncthreads();
        for (int l = threadIdx.x; l < 2048; l += 256) {
            int r = l >> 6, cc = l & 63;
            Qs[r * 68 + cc] = Q[(long long)r * NSP + c0 + cc];
            Ks[r * 68 + cc] = Kp[(long long)r * NSP + c0 + cc];
        }
        __syncthreads();
#pragma unroll
        for (int tt = 0; tt < 64; tt += 4) {
            float4 q0 = *(float4*)&Qs[ty * 68 + tt];
            float4 q1 = *(float4*)&Qs[(ty + 16) * 68 + tt];
            float4 k0 = *(float4*)&Ks[tx * 68 + tt];
            float4 k1 = *(float4*)&Ks[(tx + 16) * 68 + tt];
            a00 = fmaf(q0.x, k0.x, fmaf(q0.y, k0.y, fmaf(q0.z, k0.z, fmaf(q0.w, k0.w, a00))));
            a01 = fmaf(q0.x, k1.x, fmaf(q0.y, k1.y, fmaf(q0.z, k1.z, fmaf(q0.w, k1.w, a01))));
            a10 = fmaf(q1.x, k0.x, fmaf(q1.y, k0.y, fmaf(q1.z, k0.z, fmaf(q1.w, k0.w, a10))));
            a11 = fmaf(q1.x, k1.x, fmaf(q1.y, k1.y, fmaf(q1.z, k1.z, fmaf(q1.w, k1.w, a11))));
        }
        const float* src = (r4 < 32) ? &Qs[r4 * 68] : &Ks[(r4 - 32) * 68];
#pragma unroll
        for (int e = 0; e < 16; e++) {
            float v = src[quad * 16 + e];
            ssq = fmaf(v, v, ssq);
        }
    }
    ssq += __shfl_xor_sync(0xffffffffu, ssq, 1);
    ssq += __shfl_xor_sync(0xffffffffu, ssq, 2);

    float* out = gpart + ((long long)bh * NCH + chunk) * 1088;
    out[ty * 32 + tx]               = a00;
    out[ty * 32 + tx + 16]          = a01;
    out[(ty + 16) * 32 + tx]        = a10;
    out[(ty + 16) * 32 + tx + 16]   = a11;
    if (quad == 0) out[1024 + r4] = ssq;
}

__global__ void __launch_bounds__(1024) ca_softmax_kernel(
    const float* __restrict__ gpart, const float* __restrict__ temp,
    float* __restrict__ attn)
{
    int bh = blockIdx.x;
    int h = bh & 7;
    int t = threadIdx.x;
    const float* base = gpart + (long long)bh * NCH * 1088;

    __shared__ float ninv[64];
    if (t < 64) {
        float ss = 0.f;
#pragma unroll
        for (int c = 0; c < NCH; c++) ss += base[c * 1088 + 1024 + t];
        ninv[t] = 1.0f / fmaxf(sqrtf(ss), 1e-12f);
    }

    int i = t >> 5, j = t & 31;
    float g = 0.f;
#pragma unroll
    for (int c = 0; c < NCH; c++) g += base[c * 1088 + i * 32 + j];
    __syncthreads();

    float l = g * ninv[i] * ninv[32 + j] * temp[h];
    float m = l;
#pragma unroll
    for (int off = 16; off > 0; off >>= 1) m = fmaxf(m, __shfl_xor_sync(0xffffffffu, m, off));
    float p = fast_exp(l - m);
    float s = p;
#pragma unroll
    for (int off = 16; off > 0; off >>= 1) s += __shfl_xor_sync(0xffffffffu, s, off);
    attn[(long long)bh * 1024 + i * 32 + j] = p / s;
}

__global__ void __launch_bounds__(256) fold_kernel(const float* __restrict__ attn,
                                                   const float* __restrict__ proj_w,
                                                   float* __restrict__ Mfold)
{
    int b = blockIdx.x;
    __shared__ float As[8192];
    for (int l = threadIdx.x; l < 8192; l += 256) As[l] = attn[(long long)b * 8192 + l];
    __syncthreads();
    for (int idx = threadIdx.x; idx < 32768; idx += 256) {
        int o = idx >> 8, c = idx & 255;
        int h = c >> 5, j = c & 31;
        const float* pw = proj_w + o * 256 + h * 32;
        const float* at = As + h * 1024 + j;
        float s = 0.f;
#pragma unroll
        for (int i = 0; i < 32; i++) s = fmaf(pw[i], at[i * 32], s);
        Mfold[(long long)b * 32768 + idx] = s;
    }
}

// ----------------------------------------------------------------------------
// CSWin window attention, q-tiled (R7)
// ----------------------------------------------------------------------------
template <int DIR>
__global__ void __launch_bounds__(64) cswin_kernel(
    const float* __restrict__ cs, const float* __restrict__ lepe,
    float* __restrict__ outp)
{
    int win = blockIdx.x, h = blockIdx.y, b = blockIdx.z;
    int t = threadIdx.x;

    long long cb = (long long)b * 384 * NSP;
    long long ob = (long long)b * 128 * NSP;
    const float *qp, *kp, *vp, *lp;
    float* op;
    if (DIR == 0) {
        qp = cs + cb + (long long)(h * 8) * NSP;
        kp = cs + cb + (long long)(128 + h * 8) * NSP;
        vp = cs + cb + (long long)(256 + h * 8) * NSP;
        lp = vp;
        op = outp + ob + (long long)(h * 8) * NSP;
    } else {
        qp = cs + cb + (long long)(64 + h * 8) * NSP;
        kp = cs + cb + (long long)(192 + h * 8) * NSP;
        vp = cs + cb + (long long)(320 + h * 8) * NSP;
        lp = lepe + (long long)b * 64 * NSP + (long long)(h * 8) * NSP;
        op = outp + ob + (long long)(64 + h * 8) * NSP;
    }

    __shared__ float4 Ks[256][2];
    __shared__ float4 Vs[256][2];

    int nq[4];
    u64 q2[4][4];
#pragma unroll
    for (int qi = 0; qi < 4; qi++) {
        int tok = qi * 64 + t;
        int n = (DIR == 0) ? (((tok >> 2) << 6) + (win << 2) + (tok & 3))
                           : ((((win << 2) + (tok >> 6)) << 6) + (tok & 63));
        nq[qi] = n;
        float q[8], kr[8], vr[8];
#pragma unroll
        for (int d = 0; d < 8; d++) {
            q[d]  = qp[d * NSP + n] * 0.25f;
            kr[d] = kp[d * NSP + n];
            vr[d] = vp[d * NSP + n];
        }
        Ks[tok][0] = make_float4(kr[0], kr[1], kr[2], kr[3]);
        Ks[tok][1] = make_float4(kr[4], kr[5], kr[6], kr[7]);
        Vs[tok][0] = make_float4(vr[0], vr[1], vr[2], vr[3]);
        Vs[tok][1] = make_float4(vr[4], vr[5], vr[6], vr[7]);
        q2[qi][0] = pack2(q[0], q[1]); q2[qi][1] = pack2(q[2], q[3]);
        q2[qi][2] = pack2(q[4], q[5]); q2[qi][3] = pack2(q[6], q[7]);
    }
    __syncthreads();

    u64 acc[4][4];
    float ssum[4];
#pragma unroll
    for (int qi = 0; qi < 4; qi++) {
        ssum[qi] = 0.f;
#pragma unroll
        for (int e = 0; e < 4; e++) acc[qi][e] = 0ull;
    }

#pragma unroll 2
    for (int j = 0; j < 256; j++) {
        ulonglong2 ka  = *(const ulonglong2*)&Ks[j][0];
        ulonglong2 kb  = *(const ulonglong2*)&Ks[j][1];
        ulonglong2 va  = *(const ulonglong2*)&Vs[j][0];
        ulonglong2 vb2 = *(const ulonglong2*)&Vs[j][1];
#pragma unroll
        for (int qi = 0; qi < 4; qi++) {
            u64 s2 = fmul2(q2[qi][0], ka.x);
            s2 = ffma2(q2[qi][1], ka.y, s2);
            s2 = ffma2(q2[qi][2], kb.x, s2);
            s2 = ffma2(q2[qi][3], kb.y, s2);
            float2 sf = unpack2(s2);
            float p = fast_exp(fminf(sf.x + sf.y, 60.f));
            ssum[qi] += p;
            u64 p2 = pack2(p, p);
            acc[qi][0] = ffma2(p2, va.x,  acc[qi][0]);
            acc[qi][1] = ffma2(p2, va.y,  acc[qi][1]);
            acc[qi][2] = ffma2(p2, vb2.x, acc[qi][2]);
            acc[qi][3] = ffma2(p2, vb2.y, acc[qi][3]);
        }
    }

#pragma unroll
    for (int qi = 0; qi < 4; qi++) {
        float inv = 1.0f / ssum[qi];
        int n = nq[qi];
#pragma unroll
        for (int dp = 0; dp < 4; dp++) {
            float2 a = unpack2(acc[qi][dp]);
            op[(dp * 2 + 0) * NSP + n] = fmaf(a.x, inv, lp[(dp * 2 + 0) * NSP + n]);
            op[(dp * 2 + 1) * NSP + n] = fmaf(a.y, inv, lp[(dp * 2 + 1) * NSP + n]);
        }
    }
}

// ----------------------------------------------------------------------------
// Launch chain
// ----------------------------------------------------------------------------
extern "C" void kernel_launch(void* const* d_in, const int* in_sizes, int n_in,
                              void* d_out, int out_size)
{
    const float* x         = (const float*)d_in[0];
    const float* ca_temp   = (const float*)d_in[1];
    const float* ca_qkv_w  = (const float*)d_in[2];
    const float* ca_proj_w = (const float*)d_in[3];
    const float* cs_qk_w   = (const float*)d_in[4];
    const float* cs_v_w    = (const float*)d_in[5];
    const float* cs_vv_w   = (const float*)d_in[6];
    const float* cs_proj_w = (const float*)d_in[8];
    float* out = (float*)d_out;

    float *qkv, *gp, *catt, *Mf, *x2, *cs, *lep, *att, *wcat;
    cudaGetSymbolAddress((void**)&qkv,  g_qkv);
    cudaGetSymbolAddress((void**)&gp,   g_gpart);
    cudaGetSymbolAddress((void**)&catt, g_catt);
    cudaGetSymbolAddress((void**)&Mf,   g_M);
    cudaGetSymbolAddress((void**)&x2,   g_x2);
    cudaGetSymbolAddress((void**)&cs,   g_cs);
    cudaGetSymbolAddress((void**)&lep,  g_lepe);
    cudaGetSymbolAddress((void**)&att,  g_att);
    cudaGetSymbolAddress((void**)&wcat, g_wcat);

    cudaFuncSetAttribute(mgemm_kernel<0>, cudaFuncAttributeMaxDynamicSharedMemorySize, MG_SMEM);
    cudaFuncSetAttribute(mgemm_kernel<1>, cudaFuncAttributeMaxDynamicSharedMemorySize, MG_SMEM);

    const long long S128 = 128LL * NSP, S384 = 384LL * NSP, S768 = 768LL * NSP, S64 = 64LL * NSP;

    // 0. weight concat for fused cswin qk|v GEMM
    concat_w_kernel<<<192, 256>>>(cs_qk_w, cs_v_w, wcat);
    // 1. qkv = ca_qkv_w @ x            (M=768, K=128)  [mma fp16 1-pass]
    mgemm_kernel<0><<<dim3(32, 6, NB), 256, MG_SMEM>>>(ca_qkv_w, x, nullptr, qkv,
                                                       768, 128, 0, S128, 0, S768);
    // 2. chunked gram + sumsq
    gram_partial_kernel<<<dim3(NCH, 128), 256>>>(qkv, gp);
    // 3. channel-attn softmax
    ca_softmax_kernel<<<128, 1024>>>(gp, ca_temp, catt);
    // 4. fold proj_w through attention
    fold_kernel<<<NB, 256>>>(catt, ca_proj_w, Mf);
    // 5. x2 = x + M_b @ V              (M=128, K=256)  [mma]
    mgemm_kernel<1><<<dim3(32, 1, NB), 256, MG_SMEM>>>(Mf, qkv + 512 * NSP, x, x2,
                                                       128, 256, 32768, S768, S128, S128);
    // 6. cs = [cs_qk_w; cs_v_w] @ x2   (M=384, K=128)  [mma]
    mgemm_kernel<0><<<dim3(32, 3, NB), 256, MG_SMEM>>>(wcat, x2, nullptr, cs,
                                                       384, 128, 0, S128, 0, S384);
    // 7. lepe_v = cs_vv_w @ v_v        (M=64, K=64)    [scalar]
    sgemm_kernel<0><<<dim3(32, 1, NB), 256>>>(cs_vv_w, cs + 320 * NSP, nullptr, lep,
                                              64, 64, 0, S384, 0, S64);
    // 8/9. CSWin attention, q-tiled
    cswin_kernel<0><<<dim3(16, 8, NB), 64>>>(cs, lep, att);
    cswin_kernel<1><<<dim3(16, 8, NB), 64>>>(cs, lep, att);
    // 10. out = x2 + cs_proj_w @ att   (M=128, K=128)  [mma]
    mgemm_kernel<1><<<dim3(32, 1, NB), 256, MG_SMEM>>>(cs_proj_w, att, x2, out,
                                                       128, 128, 0, S128, S128, S128);

    (void)in_sizes; (void)n_in; (void)out_size;
}